// round 6
// baseline (speedup 1.0000x reference)
#include <cuda_runtime.h>
#include <cuda_bf16.h>
#include <cstdint>

#define NN 100000
#define EE 1200000
#define GG 128

// Scratch (device globals: no allocation anywhere)
__device__ float g_xpad [NN * 32];
__device__ float g_hbufA[NN * 64];
__device__ float g_hbufB[NN * 64];
__device__ int   g_deg[NN];
__device__ int   g_off[NN];
__device__ int   g_cur[NN];
__device__ int   g_edge[EE];
__device__ int   g_part[100352];   // block-scanned partials (98*1024)
__device__ int   g_bsum[128];

// SW128-style swizzle on byte offsets within a 128B-row tile.
__device__ __forceinline__ uint32_t swz(uint32_t off) {
    return off ^ ((off >> 3) & 0x70);
}

__device__ __forceinline__ void mma_bf16(float c[4], const uint32_t a[4],
                                         uint32_t b0, uint32_t b1) {
    asm volatile(
        "mma.sync.aligned.m16n8k16.row.col.f32.bf16.bf16.f32 "
        "{%0,%1,%2,%3}, {%4,%5,%6,%7}, {%8,%9}, {%0,%1,%2,%3};"
        : "+f"(c[0]), "+f"(c[1]), "+f"(c[2]), "+f"(c[3])
        : "r"(a[0]), "r"(a[1]), "r"(a[2]), "r"(a[3]), "r"(b0), "r"(b1));
}

__device__ __forceinline__ void split_bf16(float v, __nv_bfloat16& h, __nv_bfloat16& l) {
    h = __float2bfloat16_rn(v);
    l = __float2bfloat16_rn(v - __bfloat162float(h));
}

// ---------------------------------------------------------------------------
// CSR build kernels
// ---------------------------------------------------------------------------
__global__ void pad_init_kernel(const float* __restrict__ x,
                                float* __restrict__ xpad,
                                int* __restrict__ deg) {
    int i = blockIdx.x * blockDim.x + threadIdx.x;
    if (i >= NN * 32) return;
    int n = i >> 5, c = i & 31;
    xpad[i] = (c < 30) ? x[n * 30 + c] : 0.0f;
    if (c == 0) deg[n] = 0;
}

__global__ void count_deg_kernel(const int* __restrict__ dst, int* __restrict__ deg) {
    int e = blockIdx.x * blockDim.x + threadIdx.x;
    if (e < EE) atomicAdd(&deg[__ldg(dst + e)], 1);
}

__global__ void scan_block_kernel(const int* __restrict__ deg,
                                  int* __restrict__ part, int* __restrict__ bsum) {
    __shared__ int sh[1024];
    int tid = threadIdx.x;
    int gid = blockIdx.x * 1024 + tid;
    int v = (gid < NN) ? deg[gid] : 0;
    sh[tid] = v;
    __syncthreads();
    for (int ofs = 1; ofs < 1024; ofs <<= 1) {
        int t = 0;
        if (tid >= ofs) t = sh[tid - ofs];
        __syncthreads();
        if (tid >= ofs) sh[tid] += t;
        __syncthreads();
    }
    part[gid] = sh[tid] - v;   // exclusive
    if (tid == 1023) bsum[blockIdx.x] = sh[1023];
}

__global__ void scan_tops_kernel(int* __restrict__ bsum) {
    __shared__ int sh[128];
    int tid = threadIdx.x;
    int v = (tid < 98) ? bsum[tid] : 0;
    sh[tid] = v;
    __syncthreads();
    for (int ofs = 1; ofs < 128; ofs <<= 1) {
        int t = 0;
        if (tid >= ofs) t = sh[tid - ofs];
        __syncthreads();
        if (tid >= ofs) sh[tid] += t;
        __syncthreads();
    }
    if (tid < 98) bsum[tid] = sh[tid] - v;  // exclusive
}

__global__ void scan_add_kernel(const int* __restrict__ part,
                                const int* __restrict__ bsum,
                                int* __restrict__ off, int* __restrict__ cur) {
    int gid = blockIdx.x * 1024 + threadIdx.x;
    if (gid >= NN) return;
    int o = part[gid] + bsum[blockIdx.x];
    off[gid] = o;
    cur[gid] = o;
}

__global__ void place_kernel(const int* __restrict__ src, const int* __restrict__ dst,
                             int* __restrict__ cur, int* __restrict__ edge) {
    int e = blockIdx.x * blockDim.x + threadIdx.x;
    if (e >= EE) return;
    int d = __ldg(dst + e);
    int p = atomicAdd(&cur[d], 1);
    edge[p] = __ldg(src + e);
}

// ---------------------------------------------------------------------------
// Fused GIN layer: gather (CSR) + MLP (2 GEMMs, bf16 hi/lo split) [+ pool]
// Block: 256 threads / 128 dst nodes. 8 warps x 16 rows in the MMA phase.
// ---------------------------------------------------------------------------
__global__ void out_init_kernel(float* __restrict__ out,
                                const float* __restrict__ b_out) {
    if (threadIdx.x < GG) out[threadIdx.x] = b_out[0];
}

template <int K_IN, bool POOL>
__global__ __launch_bounds__(256) void gin_layer_kernel(
    const float* __restrict__ hin,                     // [NN, K_IN]
    const int* __restrict__ off, const int* __restrict__ deg,
    const int* __restrict__ edge,
    const float* __restrict__ eps,
    const float* __restrict__ W1, const float* __restrict__ b1,
    const float* __restrict__ W2, const float* __restrict__ b2,
    int w1Rows,
    float* __restrict__ hout,                          // !POOL
    const int* __restrict__ batch,                     // POOL
    const float* __restrict__ wout, float* __restrict__ outp) {
    __shared__ __align__(128) char sA_hi[128 * 128];   // 16KB
    __shared__ __align__(128) char sA_lo[128 * 128];   // 16KB
    __shared__ __align__(128) char sW_hi[64 * 128];    // 8KB
    __shared__ __align__(128) char sW_lo[64 * 128];    // 8KB

    constexpr int KS1 = K_IN / 16;     // k-steps GEMM1 (2 or 4)
    constexpr int HF  = K_IN / 2;      // floats gathered per thread
    constexpr int HF4 = HF / 4;

    const int tid  = threadIdx.x;
    const int warp = tid >> 5;
    const int lane = tid & 31;
    const int qr = lane >> 2;
    const int qc = lane & 3;
    const int base = blockIdx.x * 128;

    // ---- Stage W1 transposed: sW[n][k], zero k >= w1Rows ----
    for (int i = tid; i < 64 * (K_IN / 2); i += 256) {
        int n = i / (K_IN / 2), c2 = i % (K_IN / 2);
        int k0 = c2 * 2;
        float w0 = (k0     < w1Rows) ? W1[(k0    ) * 64 + n] : 0.0f;
        float w1v = (k0 + 1 < w1Rows) ? W1[(k0 + 1) * 64 + n] : 0.0f;
        __nv_bfloat16 h[2], l[2];
        split_bf16(w0, h[0], l[0]); split_bf16(w1v, h[1], l[1]);
        uint32_t o = swz((uint32_t)(n * 128 + k0 * 2));
        *(uint32_t*)(sW_hi + o) = *(uint32_t*)h;
        *(uint32_t*)(sW_lo + o) = *(uint32_t*)l;
    }

    // ---- Gather: acc = (1+eps)*h[gn] + sum_{e in CSR[gn]} h[src_e] ----
    {
        const int node = tid >> 1;
        const int half = tid & 1;
        const int gn = base + node;
        float acc[HF];
        if (gn < NN) {
            const float s = 1.0f + __ldg(eps);
            const float4* hp = (const float4*)(hin + (size_t)gn * K_IN + half * HF);
#pragma unroll
            for (int j = 0; j < HF4; j++) {
                float4 v = __ldg(hp + j);
                acc[j * 4 + 0] = s * v.x; acc[j * 4 + 1] = s * v.y;
                acc[j * 4 + 2] = s * v.z; acc[j * 4 + 3] = s * v.w;
            }
            const int e0 = __ldg(off + gn);
            const int dg = __ldg(deg + gn);
            for (int e = 0; e < dg; e++) {
                int sn = __ldg(edge + e0 + e);
                const float4* sp = (const float4*)(hin + (size_t)sn * K_IN + half * HF);
#pragma unroll
                for (int j = 0; j < HF4; j++) {
                    float4 v = __ldg(sp + j);
                    acc[j * 4 + 0] += v.x; acc[j * 4 + 1] += v.y;
                    acc[j * 4 + 2] += v.z; acc[j * 4 + 3] += v.w;
                }
            }
        } else {
#pragma unroll
            for (int j = 0; j < HF; j++) acc[j] = 0.0f;
        }
        // split to bf16 hi/lo into smem A tiles
#pragma unroll
        for (int p = 0; p < HF / 2; p++) {
            int col = half * HF + p * 2;
            __nv_bfloat16 h[2], l[2];
            split_bf16(acc[p * 2],     h[0], l[0]);
            split_bf16(acc[p * 2 + 1], h[1], l[1]);
            uint32_t o = swz((uint32_t)(node * 128 + col * 2));
            *(uint32_t*)(sA_hi + o) = *(uint32_t*)h;
            *(uint32_t*)(sA_lo + o) = *(uint32_t*)l;
        }
    }
    __syncthreads();

    float c[8][4];
#pragma unroll
    for (int n = 0; n < 8; n++)
#pragma unroll
        for (int j = 0; j < 4; j++) c[n][j] = 0.0f;

    // ---- GEMM1: C = A @ W1 (3-term hi/lo split) ----
#pragma unroll
    for (int ks = 0; ks < KS1; ks++) {
        uint32_t aH[4], aL[4];
        {
            int r0 = warp * 16 + qr;
            int k0 = ks * 16 + qc * 2;
            aH[0] = *(uint32_t*)(sA_hi + swz((uint32_t)(r0 * 128 + k0 * 2)));
            aH[1] = *(uint32_t*)(sA_hi + swz((uint32_t)((r0 + 8) * 128 + k0 * 2)));
            aH[2] = *(uint32_t*)(sA_hi + swz((uint32_t)(r0 * 128 + (k0 + 8) * 2)));
            aH[3] = *(uint32_t*)(sA_hi + swz((uint32_t)((r0 + 8) * 128 + (k0 + 8) * 2)));
            aL[0] = *(uint32_t*)(sA_lo + swz((uint32_t)(r0 * 128 + k0 * 2)));
            aL[1] = *(uint32_t*)(sA_lo + swz((uint32_t)((r0 + 8) * 128 + k0 * 2)));
            aL[2] = *(uint32_t*)(sA_lo + swz((uint32_t)(r0 * 128 + (k0 + 8) * 2)));
            aL[3] = *(uint32_t*)(sA_lo + swz((uint32_t)((r0 + 8) * 128 + (k0 + 8) * 2)));
        }
#pragma unroll
        for (int nt = 0; nt < 8; nt++) {
            int col = nt * 8 + qr;
            int k0 = ks * 16 + qc * 2;
            uint32_t bH0 = *(uint32_t*)(sW_hi + swz((uint32_t)(col * 128 + k0 * 2)));
            uint32_t bH1 = *(uint32_t*)(sW_hi + swz((uint32_t)(col * 128 + (k0 + 8) * 2)));
            uint32_t bL0 = *(uint32_t*)(sW_lo + swz((uint32_t)(col * 128 + k0 * 2)));
            uint32_t bL1 = *(uint32_t*)(sW_lo + swz((uint32_t)(col * 128 + (k0 + 8) * 2)));
            mma_bf16(c[nt], aH, bH0, bH1);
            mma_bf16(c[nt], aH, bL0, bL1);
            mma_bf16(c[nt], aL, bH0, bH1);
        }
    }

    // ---- Epilogue 1: h = relu(C + b1) -> re-split into A tiles (own rows) ----
    {
        int r0 = warp * 16 + qr;
#pragma unroll
        for (int nt = 0; nt < 8; nt++) {
            int col = nt * 8 + qc * 2;
            float bv0 = __ldg(b1 + col), bv1 = __ldg(b1 + col + 1);
            float v0 = fmaxf(c[nt][0] + bv0, 0.0f);
            float v1 = fmaxf(c[nt][1] + bv1, 0.0f);
            float v2 = fmaxf(c[nt][2] + bv0, 0.0f);
            float v3 = fmaxf(c[nt][3] + bv1, 0.0f);
            __nv_bfloat16 h[2], l[2];
            split_bf16(v0, h[0], l[0]); split_bf16(v1, h[1], l[1]);
            uint32_t o = swz((uint32_t)(r0 * 128 + col * 2));
            *(uint32_t*)(sA_hi + o) = *(uint32_t*)h;
            *(uint32_t*)(sA_lo + o) = *(uint32_t*)l;
            split_bf16(v2, h[0], l[0]); split_bf16(v3, h[1], l[1]);
            o = swz((uint32_t)((r0 + 8) * 128 + col * 2));
            *(uint32_t*)(sA_hi + o) = *(uint32_t*)h;
            *(uint32_t*)(sA_lo + o) = *(uint32_t*)l;
        }
    }
    __syncthreads();

    // ---- Restage W2 over W1 buffers ----
    for (int i = tid; i < 64 * 32; i += 256) {
        int n = i >> 5, c2 = i & 31;
        int k0 = c2 * 2;
        float w0 = W2[k0 * 64 + n];
        float w1v = W2[(k0 + 1) * 64 + n];
        __nv_bfloat16 h[2], l[2];
        split_bf16(w0, h[0], l[0]); split_bf16(w1v, h[1], l[1]);
        uint32_t o = swz((uint32_t)(n * 128 + k0 * 2));
        *(uint32_t*)(sW_hi + o) = *(uint32_t*)h;
        *(uint32_t*)(sW_lo + o) = *(uint32_t*)l;
    }
    __syncthreads();

#pragma unroll
    for (int n = 0; n < 8; n++)
#pragma unroll
        for (int j = 0; j < 4; j++) c[n][j] = 0.0f;

    // ---- GEMM2: C = h @ W2 (k always 64) ----
#pragma unroll
    for (int ks = 0; ks < 4; ks++) {
        uint32_t aH[4], aL[4];
        {
            int r0 = warp * 16 + qr;
            int k0 = ks * 16 + qc * 2;
            aH[0] = *(uint32_t*)(sA_hi + swz((uint32_t)(r0 * 128 + k0 * 2)));
            aH[1] = *(uint32_t*)(sA_hi + swz((uint32_t)((r0 + 8) * 128 + k0 * 2)));
            aH[2] = *(uint32_t*)(sA_hi + swz((uint32_t)(r0 * 128 + (k0 + 8) * 2)));
            aH[3] = *(uint32_t*)(sA_hi + swz((uint32_t)((r0 + 8) * 128 + (k0 + 8) * 2)));
            aL[0] = *(uint32_t*)(sA_lo + swz((uint32_t)(r0 * 128 + k0 * 2)));
            aL[1] = *(uint32_t*)(sA_lo + swz((uint32_t)((r0 + 8) * 128 + k0 * 2)));
            aL[2] = *(uint32_t*)(sA_lo + swz((uint32_t)(r0 * 128 + (k0 + 8) * 2)));
            aL[3] = *(uint32_t*)(sA_lo + swz((uint32_t)((r0 + 8) * 128 + (k0 + 8) * 2)));
        }
#pragma unroll
        for (int nt = 0; nt < 8; nt++) {
            int col = nt * 8 + qr;
            int k0 = ks * 16 + qc * 2;
            uint32_t bH0 = *(uint32_t*)(sW_hi + swz((uint32_t)(col * 128 + k0 * 2)));
            uint32_t bH1 = *(uint32_t*)(sW_hi + swz((uint32_t)(col * 128 + (k0 + 8) * 2)));
            uint32_t bL0 = *(uint32_t*)(sW_lo + swz((uint32_t)(col * 128 + k0 * 2)));
            uint32_t bL1 = *(uint32_t*)(sW_lo + swz((uint32_t)(col * 128 + (k0 + 8) * 2)));
            mma_bf16(c[nt], aH, bH0, bH1);
            mma_bf16(c[nt], aH, bL0, bL1);
            mma_bf16(c[nt], aL, bH0, bH1);
        }
    }

    // ---- Epilogue 2 ----
    const int r0 = warp * 16 + qr;
    const int gn0 = base + r0, gn1 = gn0 + 8;
    if (!POOL) {
#pragma unroll
        for (int nt = 0; nt < 8; nt++) {
            int col = nt * 8 + qc * 2;
            float bv0 = __ldg(b2 + col), bv1 = __ldg(b2 + col + 1);
            if (gn0 < NN)
                *(float2*)(hout + (size_t)gn0 * 64 + col) =
                    make_float2(c[nt][0] + bv0, c[nt][1] + bv1);
            if (gn1 < NN)
                *(float2*)(hout + (size_t)gn1 * 64 + col) =
                    make_float2(c[nt][2] + bv0, c[nt][3] + bv1);
        }
    } else {
        float s0 = 0.0f, s1 = 0.0f;
#pragma unroll
        for (int nt = 0; nt < 8; nt++) {
            int col = nt * 8 + qc * 2;
            float bv0 = __ldg(b2 + col), bv1 = __ldg(b2 + col + 1);
            float w0 = __ldg(wout + col), w1 = __ldg(wout + col + 1);
            s0 += (c[nt][0] + bv0) * w0 + (c[nt][1] + bv1) * w1;
            s1 += (c[nt][2] + bv0) * w0 + (c[nt][3] + bv1) * w1;
        }
        // reduce across the quad (lanes sharing qr)
        s0 += __shfl_xor_sync(0xFFFFFFFF, s0, 1);
        s0 += __shfl_xor_sync(0xFFFFFFFF, s0, 2);
        s1 += __shfl_xor_sync(0xFFFFFFFF, s1, 1);
        s1 += __shfl_xor_sync(0xFFFFFFFF, s1, 2);
        if (qc == 0) {
            if (gn0 < NN) atomicAdd(&outp[__ldg(batch + gn0)], s0);
            if (gn1 < NN) atomicAdd(&outp[__ldg(batch + gn1)], s1);
        }
    }
}

// ---------------------------------------------------------------------------
extern "C" void kernel_launch(void* const* d_in, const int* in_sizes, int n_in,
                              void* d_out, int out_size) {
    const float* x     = (const float*)d_in[0];
    const int*   ei    = (const int*)d_in[1];   // [2, E]
    const int*   batch = (const int*)d_in[2];
    const float* eps0  = (const float*)d_in[3];
    const float* w1_0  = (const float*)d_in[4];
    const float* b1_0  = (const float*)d_in[5];
    const float* w2_0  = (const float*)d_in[6];
    const float* b2_0  = (const float*)d_in[7];
    const float* eps_r = (const float*)d_in[8];
    const float* w1_r  = (const float*)d_in[9];
    const float* b1_r  = (const float*)d_in[10];
    const float* w2_r  = (const float*)d_in[11];
    const float* b2_r  = (const float*)d_in[12];
    const float* w_out = (const float*)d_in[13];
    const float* b_out = (const float*)d_in[14];

    const int* src = ei;
    const int* dst = ei + EE;

    float *xpad, *hA, *hB;
    int *deg, *off, *cur, *edge, *part, *bsum;
    cudaGetSymbolAddress((void**)&xpad, g_xpad);
    cudaGetSymbolAddress((void**)&hA,   g_hbufA);
    cudaGetSymbolAddress((void**)&hB,   g_hbufB);
    cudaGetSymbolAddress((void**)&deg,  g_deg);
    cudaGetSymbolAddress((void**)&off,  g_off);
    cudaGetSymbolAddress((void**)&cur,  g_cur);
    cudaGetSymbolAddress((void**)&edge, g_edge);
    cudaGetSymbolAddress((void**)&part, g_part);
    cudaGetSymbolAddress((void**)&bsum, g_bsum);

    float* outp = (float*)d_out;
    const int TB = 256;
    const int layer_grid = (NN + 127) / 128;

    // ---- CSR build (amortized over 4 layers) ----
    pad_init_kernel<<<(NN * 32 + TB - 1) / TB, TB>>>(x, xpad, deg);
    count_deg_kernel<<<(EE + TB - 1) / TB, TB>>>(dst, deg);
    scan_block_kernel<<<98, 1024>>>(deg, part, bsum);
    scan_tops_kernel<<<1, 128>>>(bsum);
    scan_add_kernel<<<98, 1024>>>(part, bsum, off, cur);
    place_kernel<<<(EE + TB - 1) / TB, TB>>>(src, dst, cur, edge);
    out_init_kernel<<<1, 128>>>(outp, b_out);

    // ---- Layer 0: xpad(32) -> hA ----
    gin_layer_kernel<32, false><<<layer_grid, 256>>>(
        xpad, off, deg, edge, eps0, w1_0, b1_0, w2_0, b2_0, 30,
        hA, nullptr, nullptr, nullptr);
    // ---- Layer 1: hA -> hB ----
    gin_layer_kernel<64, false><<<layer_grid, 256>>>(
        hA, off, deg, edge, eps_r + 0, w1_r, b1_r, w2_r, b2_r, 64,
        hB, nullptr, nullptr, nullptr);
    // ---- Layer 2: hB -> hA ----
    gin_layer_kernel<64, false><<<layer_grid, 256>>>(
        hB, off, deg, edge, eps_r + 1, w1_r + 4096, b1_r + 64, w2_r + 4096, b2_r + 64, 64,
        hA, nullptr, nullptr, nullptr);
    // ---- Layer 3 (fused pool): hA -> out ----
    gin_layer_kernel<64, true><<<layer_grid, 256>>>(
        hA, off, deg, edge, eps_r + 2, w1_r + 8192, b1_r + 128, w2_r + 8192, b2_r + 128, 64,
        nullptr, batch, w_out, outp);
}

// round 7
// speedup vs baseline: 1.4961x; 1.4961x over previous
#include <cuda_runtime.h>
#include <cuda_bf16.h>
#include <cstdint>

#define NN 100000
#define EE 1200000
#define GG 128

// Scratch (device globals: no allocation anywhere)
__device__ float g_xpad[NN * 32];
__device__ float g_agg [NN * 64];
__device__ float g_hbuf[NN * 64];
__device__ int   g_deg[NN];
__device__ int   g_off[NN];
__device__ int   g_cur[NN];
__device__ int   g_edge[EE];
__device__ int   g_part[100352];   // 98*1024 block-scanned partials
__device__ int   g_bsum[128];

// SW128-style swizzle on byte offsets within a 128B-row tile.
__device__ __forceinline__ uint32_t swz(uint32_t off) {
    return off ^ ((off >> 3) & 0x70);
}

__device__ __forceinline__ void mma_bf16(float c[4], const uint32_t a[4],
                                         uint32_t b0, uint32_t b1) {
    asm volatile(
        "mma.sync.aligned.m16n8k16.row.col.f32.bf16.bf16.f32 "
        "{%0,%1,%2,%3}, {%4,%5,%6,%7}, {%8,%9}, {%0,%1,%2,%3};"
        : "+f"(c[0]), "+f"(c[1]), "+f"(c[2]), "+f"(c[3])
        : "r"(a[0]), "r"(a[1]), "r"(a[2]), "r"(a[3]), "r"(b0), "r"(b1));
}

__device__ __forceinline__ void split_bf16(float v, __nv_bfloat16& h, __nv_bfloat16& l) {
    h = __float2bfloat16_rn(v);
    l = __float2bfloat16_rn(v - __bfloat162float(h));
}

// ---------------------------------------------------------------------------
// CSR build
// ---------------------------------------------------------------------------
__global__ void pad_init_kernel(const float* __restrict__ x,
                                float* __restrict__ xpad,
                                int* __restrict__ deg) {
    int i = blockIdx.x * blockDim.x + threadIdx.x;
    if (i >= NN * 32) return;
    int n = i >> 5, c = i & 31;
    xpad[i] = (c < 30) ? x[n * 30 + c] : 0.0f;
    if (c == 0) deg[n] = 0;
}

__global__ void count_deg_kernel(const int* __restrict__ dst, int* __restrict__ deg) {
    int e = blockIdx.x * blockDim.x + threadIdx.x;
    if (e < EE) atomicAdd(&deg[__ldg(dst + e)], 1);
}

__global__ void scan_block_kernel(const int* __restrict__ deg,
                                  int* __restrict__ part, int* __restrict__ bsum) {
    __shared__ int sh[1024];
    int tid = threadIdx.x;
    int gid = blockIdx.x * 1024 + tid;
    int v = (gid < NN) ? deg[gid] : 0;
    sh[tid] = v;
    __syncthreads();
    for (int ofs = 1; ofs < 1024; ofs <<= 1) {
        int t = 0;
        if (tid >= ofs) t = sh[tid - ofs];
        __syncthreads();
        if (tid >= ofs) sh[tid] += t;
        __syncthreads();
    }
    part[gid] = sh[tid] - v;   // exclusive
    if (tid == 1023) bsum[blockIdx.x] = sh[1023];
}

// Each block redundantly scans the 98 block sums in smem, then adds.
__global__ void scan_add_kernel(const int* __restrict__ part,
                                const int* __restrict__ bsum,
                                int* __restrict__ off, int* __restrict__ cur) {
    __shared__ int sh[128];
    int tid = threadIdx.x;
    if (tid < 128) {
        int v = (tid < 98) ? bsum[tid] : 0;
        sh[tid] = v;
    }
    __syncthreads();
    if (tid < 128) {
        for (int ofs = 1; ofs < 128; ofs <<= 1) {
            int t = 0;
            if (tid >= ofs) t = sh[tid - ofs];
            __syncthreads();
            if (tid >= ofs) sh[tid] += t;
            __syncthreads();
        }
    } else {
        for (int ofs = 1; ofs < 128; ofs <<= 1) { __syncthreads(); __syncthreads(); }
    }
    __syncthreads();
    int gid = blockIdx.x * 1024 + tid;
    if (gid >= NN) return;
    int blk_excl = (blockIdx.x == 0) ? 0 : sh[blockIdx.x - 1];
    int o = part[gid] + blk_excl;
    off[gid] = o;
    cur[gid] = o;
}

__global__ void place_kernel(const int* __restrict__ src, const int* __restrict__ dst,
                             int* __restrict__ cur, int* __restrict__ edge) {
    int e = blockIdx.x * blockDim.x + threadIdx.x;
    if (e >= EE) return;
    int d = __ldg(dst + e);
    int p = atomicAdd(&cur[d], 1);
    edge[p] = __ldg(src + e);
}

__global__ void out_init_kernel(float* __restrict__ out,
                                const float* __restrict__ b_out) {
    if (threadIdx.x < GG) out[threadIdx.x] = b_out[0];
}

// ---------------------------------------------------------------------------
// Gather: agg[n] = (1+eps)*h[n] + sum_{e in CSR[n]} h[src_e]
// K/4 lanes per node (float4 per lane); warp covers 128/K nodes. No smem,
// low regs -> high occupancy; edge loop unrolled x2 for MLP.
// ---------------------------------------------------------------------------
template <int K>
__global__ __launch_bounds__(256) void gather_kernel(
    const float* __restrict__ hin, float* __restrict__ agg,
    const int* __restrict__ off, const int* __restrict__ deg,
    const int* __restrict__ edge, const float* __restrict__ eps) {
    constexpr int L = K / 4;             // lanes per node
    const int tid = blockIdx.x * 256 + threadIdx.x;
    const int gn = tid / L;
    const int sub = tid % L;
    if (gn >= NN) return;

    const float s = 1.0f + __ldg(eps);
    float4 v0 = __ldg((const float4*)(hin + (size_t)gn * K + sub * 4));
    float4 acc = make_float4(s * v0.x, s * v0.y, s * v0.z, s * v0.w);

    const int e0 = __ldg(off + gn);
    const int dg = __ldg(deg + gn);
    int e = 0;
    for (; e + 2 <= dg; e += 2) {
        int sn0 = __ldg(edge + e0 + e);
        int sn1 = __ldg(edge + e0 + e + 1);
        float4 a = __ldg((const float4*)(hin + (size_t)sn0 * K + sub * 4));
        float4 b = __ldg((const float4*)(hin + (size_t)sn1 * K + sub * 4));
        acc.x += a.x + b.x; acc.y += a.y + b.y;
        acc.z += a.z + b.z; acc.w += a.w + b.w;
    }
    if (e < dg) {
        int sn0 = __ldg(edge + e0 + e);
        float4 a = __ldg((const float4*)(hin + (size_t)sn0 * K + sub * 4));
        acc.x += a.x; acc.y += a.y; acc.z += a.z; acc.w += a.w;
    }
    *(float4*)(agg + (size_t)gn * K + sub * 4) = acc;
}

// ---------------------------------------------------------------------------
// Fused GIN MLP (R4-proven): out = relu(A@W1+b1)@W2+b2 per 128-node tile.
// bf16 hi/lo split (3 terms), fp32 accumulate. POOL folds h.w_out into out[g].
// ---------------------------------------------------------------------------
template <int K_IN, bool POOL>
__global__ __launch_bounds__(128) void fused_mlp_kernel(
    const float* __restrict__ A, const float* __restrict__ W1,
    const float* __restrict__ b1, const float* __restrict__ W2,
    const float* __restrict__ b2, int w1Rows,
    float* __restrict__ out,
    const int* __restrict__ batch,
    const float* __restrict__ wout, float* __restrict__ outp) {
    __shared__ __align__(128) char sA_hi[128 * 128];  // 16KB
    __shared__ __align__(128) char sA_lo[128 * 128];  // 16KB
    __shared__ __align__(128) char sW_hi[64 * 128];   // 8KB
    __shared__ __align__(128) char sW_lo[64 * 128];   // 8KB

    const int tid  = threadIdx.x;
    const int warp = tid >> 5;
    const int lane = tid & 31;
    const int qr = lane >> 2;
    const int qc = lane & 3;
    const int base = blockIdx.x * 128;

    // ---- Stage A: [128][K_IN] fp32 -> bf16 hi/lo, swizzled, zero-pad to 64 ----
    for (int i = tid; i < 128 * 16; i += 128) {
        int row = i >> 4, chunk = i & 15;
        float4 v = make_float4(0.f, 0.f, 0.f, 0.f);
        int gn = base + row;
        if (gn < NN && chunk * 4 < K_IN)
            v = *(const float4*)(A + (size_t)gn * K_IN + chunk * 4);
        __nv_bfloat16 h[4], l[4];
        split_bf16(v.x, h[0], l[0]); split_bf16(v.y, h[1], l[1]);
        split_bf16(v.z, h[2], l[2]); split_bf16(v.w, h[3], l[3]);
        uint32_t off = swz((uint32_t)(row * 128 + chunk * 8));
        *(uint2*)(sA_hi + off) = *(uint2*)h;
        *(uint2*)(sA_lo + off) = *(uint2*)l;
    }
    // ---- Stage W1 transposed ----
    for (int i = tid; i < 64 * 32; i += 128) {
        int n = i >> 5, c2 = i & 31;
        int k0 = c2 * 2;
        float w0 = (k0     < w1Rows) ? W1[(k0    ) * 64 + n] : 0.0f;
        float w1v = (k0 + 1 < w1Rows) ? W1[(k0 + 1) * 64 + n] : 0.0f;
        __nv_bfloat16 h[2], l[2];
        split_bf16(w0, h[0], l[0]); split_bf16(w1v, h[1], l[1]);
        uint32_t off = swz((uint32_t)(n * 128 + k0 * 2));
        *(uint32_t*)(sW_hi + off) = *(uint32_t*)h;
        *(uint32_t*)(sW_lo + off) = *(uint32_t*)l;
    }
    __syncthreads();

    float c[2][8][4];
#pragma unroll
    for (int m = 0; m < 2; m++)
#pragma unroll
        for (int n = 0; n < 8; n++)
#pragma unroll
            for (int j = 0; j < 4; j++) c[m][n][j] = 0.0f;

    // ---- GEMM1 ----
#pragma unroll
    for (int ks = 0; ks < 4; ks++) {
        uint32_t aH[2][4], aL[2][4];
#pragma unroll
        for (int m = 0; m < 2; m++) {
            int r0 = warp * 32 + m * 16 + qr;
            int k0 = ks * 16 + qc * 2;
            aH[m][0] = *(uint32_t*)(sA_hi + swz((uint32_t)(r0 * 128 + k0 * 2)));
            aH[m][1] = *(uint32_t*)(sA_hi + swz((uint32_t)((r0 + 8) * 128 + k0 * 2)));
            aH[m][2] = *(uint32_t*)(sA_hi + swz((uint32_t)(r0 * 128 + (k0 + 8) * 2)));
            aH[m][3] = *(uint32_t*)(sA_hi + swz((uint32_t)((r0 + 8) * 128 + (k0 + 8) * 2)));
            aL[m][0] = *(uint32_t*)(sA_lo + swz((uint32_t)(r0 * 128 + k0 * 2)));
            aL[m][1] = *(uint32_t*)(sA_lo + swz((uint32_t)((r0 + 8) * 128 + k0 * 2)));
            aL[m][2] = *(uint32_t*)(sA_lo + swz((uint32_t)(r0 * 128 + (k0 + 8) * 2)));
            aL[m][3] = *(uint32_t*)(sA_lo + swz((uint32_t)((r0 + 8) * 128 + (k0 + 8) * 2)));
        }
#pragma unroll
        for (int nt = 0; nt < 8; nt++) {
            int col = nt * 8 + qr;
            int k0 = ks * 16 + qc * 2;
            uint32_t bH0 = *(uint32_t*)(sW_hi + swz((uint32_t)(col * 128 + k0 * 2)));
            uint32_t bH1 = *(uint32_t*)(sW_hi + swz((uint32_t)(col * 128 + (k0 + 8) * 2)));
            uint32_t bL0 = *(uint32_t*)(sW_lo + swz((uint32_t)(col * 128 + k0 * 2)));
            uint32_t bL1 = *(uint32_t*)(sW_lo + swz((uint32_t)(col * 128 + (k0 + 8) * 2)));
#pragma unroll
            for (int m = 0; m < 2; m++) {
                mma_bf16(c[m][nt], aH[m], bH0, bH1);
                mma_bf16(c[m][nt], aH[m], bL0, bL1);
                mma_bf16(c[m][nt], aL[m], bH0, bH1);
            }
        }
    }

    // ---- Epilogue 1: h = relu(C + b1); re-split into A tiles ----
#pragma unroll
    for (int m = 0; m < 2; m++) {
        int r0 = warp * 32 + m * 16 + qr;
#pragma unroll
        for (int nt = 0; nt < 8; nt++) {
            int col = nt * 8 + qc * 2;
            float bv0 = __ldg(b1 + col), bv1 = __ldg(b1 + col + 1);
            float v0 = fmaxf(c[m][nt][0] + bv0, 0.0f);
            float v1 = fmaxf(c[m][nt][1] + bv1, 0.0f);
            float v2 = fmaxf(c[m][nt][2] + bv0, 0.0f);
            float v3 = fmaxf(c[m][nt][3] + bv1, 0.0f);
            __nv_bfloat16 h[2], l[2];
            split_bf16(v0, h[0], l[0]); split_bf16(v1, h[1], l[1]);
            uint32_t off = swz((uint32_t)(r0 * 128 + col * 2));
            *(uint32_t*)(sA_hi + off) = *(uint32_t*)h;
            *(uint32_t*)(sA_lo + off) = *(uint32_t*)l;
            split_bf16(v2, h[0], l[0]); split_bf16(v3, h[1], l[1]);
            off = swz((uint32_t)((r0 + 8) * 128 + col * 2));
            *(uint32_t*)(sA_hi + off) = *(uint32_t*)h;
            *(uint32_t*)(sA_lo + off) = *(uint32_t*)l;
        }
    }
    __syncthreads();

    // ---- Restage W2 ----
    for (int i = tid; i < 64 * 32; i += 128) {
        int n = i >> 5, c2 = i & 31;
        int k0 = c2 * 2;
        float w0 = W2[k0 * 64 + n];
        float w1v = W2[(k0 + 1) * 64 + n];
        __nv_bfloat16 h[2], l[2];
        split_bf16(w0, h[0], l[0]); split_bf16(w1v, h[1], l[1]);
        uint32_t off = swz((uint32_t)(n * 128 + k0 * 2));
        *(uint32_t*)(sW_hi + off) = *(uint32_t*)h;
        *(uint32_t*)(sW_lo + off) = *(uint32_t*)l;
    }
    __syncthreads();

#pragma unroll
    for (int m = 0; m < 2; m++)
#pragma unroll
        for (int n = 0; n < 8; n++)
#pragma unroll
            for (int j = 0; j < 4; j++) c[m][n][j] = 0.0f;

    // ---- GEMM2 ----
#pragma unroll
    for (int ks = 0; ks < 4; ks++) {
        uint32_t aH[2][4], aL[2][4];
#pragma unroll
        for (int m = 0; m < 2; m++) {
            int r0 = warp * 32 + m * 16 + qr;
            int k0 = ks * 16 + qc * 2;
            aH[m][0] = *(uint32_t*)(sA_hi + swz((uint32_t)(r0 * 128 + k0 * 2)));
            aH[m][1] = *(uint32_t*)(sA_hi + swz((uint32_t)((r0 + 8) * 128 + k0 * 2)));
            aH[m][2] = *(uint32_t*)(sA_hi + swz((uint32_t)(r0 * 128 + (k0 + 8) * 2)));
            aH[m][3] = *(uint32_t*)(sA_hi + swz((uint32_t)((r0 + 8) * 128 + (k0 + 8) * 2)));
            aL[m][0] = *(uint32_t*)(sA_lo + swz((uint32_t)(r0 * 128 + k0 * 2)));
            aL[m][1] = *(uint32_t*)(sA_lo + swz((uint32_t)((r0 + 8) * 128 + k0 * 2)));
            aL[m][2] = *(uint32_t*)(sA_lo + swz((uint32_t)(r0 * 128 + (k0 + 8) * 2)));
            aL[m][3] = *(uint32_t*)(sA_lo + swz((uint32_t)((r0 + 8) * 128 + (k0 + 8) * 2)));
        }
#pragma unroll
        for (int nt = 0; nt < 8; nt++) {
            int col = nt * 8 + qr;
            int k0 = ks * 16 + qc * 2;
            uint32_t bH0 = *(uint32_t*)(sW_hi + swz((uint32_t)(col * 128 + k0 * 2)));
            uint32_t bH1 = *(uint32_t*)(sW_hi + swz((uint32_t)(col * 128 + (k0 + 8) * 2)));
            uint32_t bL0 = *(uint32_t*)(sW_lo + swz((uint32_t)(col * 128 + k0 * 2)));
            uint32_t bL1 = *(uint32_t*)(sW_lo + swz((uint32_t)(col * 128 + (k0 + 8) * 2)));
#pragma unroll
            for (int m = 0; m < 2; m++) {
                mma_bf16(c[m][nt], aH[m], bH0, bH1);
                mma_bf16(c[m][nt], aH[m], bL0, bL1);
                mma_bf16(c[m][nt], aL[m], bH0, bH1);
            }
        }
    }

    // ---- Epilogue 2 ----
    if (!POOL) {
#pragma unroll
        for (int m = 0; m < 2; m++) {
            int r0 = warp * 32 + m * 16 + qr;
            int gn0 = base + r0, gn1 = gn0 + 8;
#pragma unroll
            for (int nt = 0; nt < 8; nt++) {
                int col = nt * 8 + qc * 2;
                float bv0 = __ldg(b2 + col), bv1 = __ldg(b2 + col + 1);
                if (gn0 < NN)
                    *(float2*)(out + (size_t)gn0 * 64 + col) =
                        make_float2(c[m][nt][0] + bv0, c[m][nt][1] + bv1);
                if (gn1 < NN)
                    *(float2*)(out + (size_t)gn1 * 64 + col) =
                        make_float2(c[m][nt][2] + bv0, c[m][nt][3] + bv1);
            }
        }
    } else {
#pragma unroll
        for (int m = 0; m < 2; m++) {
            int r0 = warp * 32 + m * 16 + qr;
            int gn0 = base + r0, gn1 = gn0 + 8;
            float s0 = 0.0f, s1 = 0.0f;
#pragma unroll
            for (int nt = 0; nt < 8; nt++) {
                int col = nt * 8 + qc * 2;
                float bv0 = __ldg(b2 + col), bv1 = __ldg(b2 + col + 1);
                float w0 = __ldg(wout + col), w1 = __ldg(wout + col + 1);
                s0 += (c[m][nt][0] + bv0) * w0 + (c[m][nt][1] + bv1) * w1;
                s1 += (c[m][nt][2] + bv0) * w0 + (c[m][nt][3] + bv1) * w1;
            }
            s0 += __shfl_xor_sync(0xFFFFFFFF, s0, 1);
            s0 += __shfl_xor_sync(0xFFFFFFFF, s0, 2);
            s1 += __shfl_xor_sync(0xFFFFFFFF, s1, 1);
            s1 += __shfl_xor_sync(0xFFFFFFFF, s1, 2);
            if (qc == 0) {
                if (gn0 < NN) atomicAdd(&outp[__ldg(batch + gn0)], s0);
                if (gn1 < NN) atomicAdd(&outp[__ldg(batch + gn1)], s1);
            }
        }
    }
}

// ---------------------------------------------------------------------------
extern "C" void kernel_launch(void* const* d_in, const int* in_sizes, int n_in,
                              void* d_out, int out_size) {
    const float* x     = (const float*)d_in[0];
    const int*   ei    = (const int*)d_in[1];   // [2, E]
    const int*   batch = (const int*)d_in[2];
    const float* eps0  = (const float*)d_in[3];
    const float* w1_0  = (const float*)d_in[4];
    const float* b1_0  = (const float*)d_in[5];
    const float* w2_0  = (const float*)d_in[6];
    const float* b2_0  = (const float*)d_in[7];
    const float* eps_r = (const float*)d_in[8];
    const float* w1_r  = (const float*)d_in[9];
    const float* b1_r  = (const float*)d_in[10];
    const float* w2_r  = (const float*)d_in[11];
    const float* b2_r  = (const float*)d_in[12];
    const float* w_out = (const float*)d_in[13];
    const float* b_out = (const float*)d_in[14];

    const int* src = ei;
    const int* dst = ei + EE;

    float *xpad, *agg, *hbuf;
    int *deg, *off, *cur, *edge, *part, *bsum;
    cudaGetSymbolAddress((void**)&xpad, g_xpad);
    cudaGetSymbolAddress((void**)&agg,  g_agg);
    cudaGetSymbolAddress((void**)&hbuf, g_hbuf);
    cudaGetSymbolAddress((void**)&deg,  g_deg);
    cudaGetSymbolAddress((void**)&off,  g_off);
    cudaGetSymbolAddress((void**)&cur,  g_cur);
    cudaGetSymbolAddress((void**)&edge, g_edge);
    cudaGetSymbolAddress((void**)&part, g_part);
    cudaGetSymbolAddress((void**)&bsum, g_bsum);

    float* outp = (float*)d_out;
    const int TB = 256;
    const int mlp_grid = (NN + 127) / 128;

    // ---- CSR build (one-time) + prep ----
    pad_init_kernel<<<(NN * 32 + TB - 1) / TB, TB>>>(x, xpad, deg);
    count_deg_kernel<<<(EE + TB - 1) / TB, TB>>>(dst, deg);
    scan_block_kernel<<<98, 1024>>>(deg, part, bsum);
    scan_add_kernel<<<98, 1024>>>(part, bsum, off, cur);
    place_kernel<<<(EE + TB - 1) / TB, TB>>>(src, dst, cur, edge);
    out_init_kernel<<<1, 128>>>(outp, b_out);

    // ---- Layer 0 (K=32) ----
    gather_kernel<32><<<(NN * 8 + 255) / 256, 256>>>(xpad, agg, off, deg, edge, eps0);
    fused_mlp_kernel<32, false><<<mlp_grid, 128>>>(agg, w1_0, b1_0, w2_0, b2_0, 30,
                                                   hbuf, nullptr, nullptr, nullptr);
    // ---- Layers 1..2 ----
    for (int i = 0; i < 2; i++) {
        gather_kernel<64><<<(NN * 16 + 255) / 256, 256>>>(hbuf, agg, off, deg, edge, eps_r + i);
        fused_mlp_kernel<64, false><<<mlp_grid, 128>>>(agg, w1_r + i * 4096, b1_r + i * 64,
                                                       w2_r + i * 4096, b2_r + i * 64, 64,
                                                       hbuf, nullptr, nullptr, nullptr);
    }
    // ---- Layer 3 (fused pool) ----
    gather_kernel<64><<<(NN * 16 + 255) / 256, 256>>>(hbuf, agg, off, deg, edge, eps_r + 2);
    fused_mlp_kernel<64, true><<<mlp_grid, 128>>>(agg, w1_r + 8192, b1_r + 128,
                                                  w2_r + 8192, b2_r + 128, 64,
                                                  nullptr, batch, w_out, outp);
}

// round 8
// speedup vs baseline: 1.6231x; 1.0849x over previous
#include <cuda_runtime.h>
#include <cuda_bf16.h>
#include <cstdint>
#include <cstring>

#define NN 100000
#define EE 1200000
#define GG 128

// Scratch (device globals: no allocation anywhere)
__device__ float    g_xpad[NN * 32];
__device__ float    g_hbuf[NN * 64];
__device__ __align__(16) uint16_t g_aggh[NN * 64];
__device__ __align__(16) uint16_t g_aggl[NN * 64];
__device__ int   g_deg[NN];
__device__ int   g_off[NN];
__device__ int   g_cur[NN];
__device__ int   g_edge[EE];
__device__ int   g_part[100352];   // 98*1024 block-scanned partials
__device__ int   g_bsum[128];

// ---------------------------------------------------------------------------
// Helpers
// ---------------------------------------------------------------------------
__device__ __forceinline__ uint32_t smem_u32(const void* p) {
    uint32_t a;
    asm("{ .reg .u64 t; cvta.to.shared.u64 t, %1; cvt.u32.u64 %0, t; }"
        : "=r"(a) : "l"(p));
    return a;
}

// Swizzled row base: swz(row*128 + kb) == rb(row) ^ kb  for kb < 128 (no carry)
__device__ __forceinline__ uint32_t rb(int row) {
    return (uint32_t)(row * 128) ^ (((uint32_t)row & 7u) << 4);
}

__device__ __forceinline__ void ldm_x4(uint32_t r[4], uint32_t addr) {
    asm volatile("ldmatrix.sync.aligned.m8n8.x4.shared.b16 {%0,%1,%2,%3}, [%4];"
                 : "=r"(r[0]), "=r"(r[1]), "=r"(r[2]), "=r"(r[3]) : "r"(addr));
}

__device__ __forceinline__ void mma_bf16(float c[4], const uint32_t a[4],
                                         uint32_t b0, uint32_t b1) {
    asm volatile(
        "mma.sync.aligned.m16n8k16.row.col.f32.bf16.bf16.f32 "
        "{%0,%1,%2,%3}, {%4,%5,%6,%7}, {%8,%9}, {%0,%1,%2,%3};"
        : "+f"(c[0]), "+f"(c[1]), "+f"(c[2]), "+f"(c[3])
        : "r"(a[0]), "r"(a[1]), "r"(a[2]), "r"(a[3]), "r"(b0), "r"(b1));
}

__device__ __forceinline__ void split_bf16(float v, __nv_bfloat16& h, __nv_bfloat16& l) {
    h = __float2bfloat16_rn(v);
    l = __float2bfloat16_rn(v - __bfloat162float(h));
}

// Split+pack two floats: returns hi-pair (bf16x2 bits), writes lo-pair.
__device__ __forceinline__ uint32_t packsplit(float a, float b, uint32_t& lopack) {
    __nv_bfloat16 ha, la, hb, lb;
    split_bf16(a, ha, la);
    split_bf16(b, hb, lb);
    uint16_t ua, ub, va, vb;
    memcpy(&ua, &ha, 2); memcpy(&ub, &hb, 2);
    memcpy(&va, &la, 2); memcpy(&vb, &lb, 2);
    lopack = (uint32_t)va | ((uint32_t)vb << 16);
    return (uint32_t)ua | ((uint32_t)ub << 16);
}

// ---------------------------------------------------------------------------
// CSR build
// ---------------------------------------------------------------------------
__global__ void pad_init_kernel(const float* __restrict__ x,
                                float* __restrict__ xpad,
                                int* __restrict__ deg) {
    int i = blockIdx.x * blockDim.x + threadIdx.x;
    if (i >= NN * 32) return;
    int n = i >> 5, c = i & 31;
    xpad[i] = (c < 30) ? x[n * 30 + c] : 0.0f;
    if (c == 0) deg[n] = 0;
}

__global__ void count_deg_kernel(const int* __restrict__ dst, int* __restrict__ deg) {
    int e = blockIdx.x * blockDim.x + threadIdx.x;
    if (e < EE) atomicAdd(&deg[__ldg(dst + e)], 1);
}

__global__ void scan_block_kernel(const int* __restrict__ deg,
                                  int* __restrict__ part, int* __restrict__ bsum) {
    __shared__ int sh[1024];
    int tid = threadIdx.x;
    int gid = blockIdx.x * 1024 + tid;
    int v = (gid < NN) ? deg[gid] : 0;
    sh[tid] = v;
    __syncthreads();
    for (int ofs = 1; ofs < 1024; ofs <<= 1) {
        int t = 0;
        if (tid >= ofs) t = sh[tid - ofs];
        __syncthreads();
        if (tid >= ofs) sh[tid] += t;
        __syncthreads();
    }
    part[gid] = sh[tid] - v;   // exclusive
    if (tid == 1023) bsum[blockIdx.x] = sh[1023];
}

__global__ void scan_add_kernel(const int* __restrict__ part,
                                const int* __restrict__ bsum,
                                int* __restrict__ off, int* __restrict__ cur) {
    __shared__ int sh[128];
    int tid = threadIdx.x;
    if (tid < 128) {
        int v = (tid < 98) ? bsum[tid] : 0;
        sh[tid] = v;
    }
    __syncthreads();
    if (tid < 128) {
        for (int ofs = 1; ofs < 128; ofs <<= 1) {
            int t = 0;
            if (tid >= ofs) t = sh[tid - ofs];
            __syncthreads();
            if (tid >= ofs) sh[tid] += t;
            __syncthreads();
        }
    } else {
        for (int ofs = 1; ofs < 128; ofs <<= 1) { __syncthreads(); __syncthreads(); }
    }
    __syncthreads();
    int gid = blockIdx.x * 1024 + tid;
    if (gid >= NN) return;
    int blk_excl = (blockIdx.x == 0) ? 0 : sh[blockIdx.x - 1];
    int o = part[gid] + blk_excl;
    off[gid] = o;
    cur[gid] = o;
}

__global__ void place_kernel(const int* __restrict__ src, const int* __restrict__ dst,
                             int* __restrict__ cur, int* __restrict__ edge) {
    int e = blockIdx.x * blockDim.x + threadIdx.x;
    if (e >= EE) return;
    int d = __ldg(dst + e);
    int p = atomicAdd(&cur[d], 1);
    edge[p] = __ldg(src + e);
}

__global__ void out_init_kernel(float* __restrict__ out,
                                const float* __restrict__ b_out) {
    if (threadIdx.x < GG) out[threadIdx.x] = b_out[0];
}

// ---------------------------------------------------------------------------
// Gather: acc = (1+eps)*h[n] + sum h[src_e]; OUTPUT = bf16 hi/lo split arrays.
// K/4 lanes per node (float4 per lane). Memory-bound; split ALU hides here.
// ---------------------------------------------------------------------------
template <int K>
__global__ __launch_bounds__(256) void gather_kernel(
    const float* __restrict__ hin,
    uint16_t* __restrict__ agh, uint16_t* __restrict__ agl,
    const int* __restrict__ off, const int* __restrict__ deg,
    const int* __restrict__ edge, const float* __restrict__ eps) {
    constexpr int L = K / 4;
    const int tid = blockIdx.x * 256 + threadIdx.x;
    const int gn = tid / L;
    const int sub = tid % L;
    if (gn >= NN) return;

    const float s = 1.0f + __ldg(eps);
    float4 v0 = __ldg((const float4*)(hin + (size_t)gn * K + sub * 4));
    float4 acc = make_float4(s * v0.x, s * v0.y, s * v0.z, s * v0.w);

    const int e0 = __ldg(off + gn);
    const int dg = __ldg(deg + gn);
    int e = 0;
    for (; e + 2 <= dg; e += 2) {
        int sn0 = __ldg(edge + e0 + e);
        int sn1 = __ldg(edge + e0 + e + 1);
        float4 a = __ldg((const float4*)(hin + (size_t)sn0 * K + sub * 4));
        float4 b = __ldg((const float4*)(hin + (size_t)sn1 * K + sub * 4));
        acc.x += a.x + b.x; acc.y += a.y + b.y;
        acc.z += a.z + b.z; acc.w += a.w + b.w;
    }
    if (e < dg) {
        int sn0 = __ldg(edge + e0 + e);
        float4 a = __ldg((const float4*)(hin + (size_t)sn0 * K + sub * 4));
        acc.x += a.x; acc.y += a.y; acc.z += a.z; acc.w += a.w;
    }

    uint2 hv, lv;
    hv.x = packsplit(acc.x, acc.y, lv.x);
    hv.y = packsplit(acc.z, acc.w, lv.y);
    *(uint2*)(agh + (size_t)gn * K + sub * 4) = hv;
    *(uint2*)(agl + (size_t)gn * K + sub * 4) = lv;
}

// ---------------------------------------------------------------------------
// GEMM core: C[2][8][4] += A(smem swz, hi/lo) @ W(smem swz, hi/lo), 3 terms.
// ldmatrix-based fragment loads; one XOR per load for swizzled addressing.
// ---------------------------------------------------------------------------
template <int KS>
__device__ __forceinline__ void do_gemm(float c[2][8][4],
                                        const uint32_t aBH[2], const uint32_t aBL[2],
                                        const uint32_t bBH[4], const uint32_t bBL[4]) {
#pragma unroll
    for (int ks = 0; ks < KS; ks++) {
        const uint32_t kx = ks * 32;
        uint32_t aH[2][4], aL[2][4];
#pragma unroll
        for (int m = 0; m < 2; m++) {
            ldm_x4(aH[m], aBH[m] ^ kx);
            ldm_x4(aL[m], aBL[m] ^ kx);
        }
#pragma unroll
        for (int p = 0; p < 4; p++) {
            uint32_t bh[4], bl[4];
            ldm_x4(bh, bBH[p] ^ kx);
            ldm_x4(bl, bBL[p] ^ kx);
#pragma unroll
            for (int s = 0; s < 2; s++) {
                const int nt = 2 * p + s;
#pragma unroll
                for (int m = 0; m < 2; m++) {
                    mma_bf16(c[m][nt], aH[m], bh[s * 2], bh[s * 2 + 1]);
                    mma_bf16(c[m][nt], aH[m], bl[s * 2], bl[s * 2 + 1]);
                    mma_bf16(c[m][nt], aL[m], bh[s * 2], bh[s * 2 + 1]);
                }
            }
        }
    }
}

// ---------------------------------------------------------------------------
// Fused GIN MLP: out = relu(A@W1+b1)@W2+b2 per 128-node tile.
// A arrives pre-split (hi/lo bf16) from the gather. POOL folds h.w_out.
// ---------------------------------------------------------------------------
template <int K_IN, bool POOL>
__global__ __launch_bounds__(128) void fused_mlp_kernel(
    const uint16_t* __restrict__ Ah, const uint16_t* __restrict__ Al,
    const float* __restrict__ W1, const float* __restrict__ b1,
    const float* __restrict__ W2, const float* __restrict__ b2, int w1Rows,
    float* __restrict__ out,
    const int* __restrict__ batch,
    const float* __restrict__ wout, float* __restrict__ outp) {
    __shared__ __align__(128) char sA_hi[128 * 128];  // 16KB
    __shared__ __align__(128) char sA_lo[128 * 128];  // 16KB
    __shared__ __align__(128) char sW_hi[64 * 128];   // 8KB
    __shared__ __align__(128) char sW_lo[64 * 128];   // 8KB

    const int tid  = threadIdx.x;
    const int warp = tid >> 5;
    const int lane = tid & 31;
    const int qr = lane >> 2;
    const int qc = lane & 3;
    const int g  = lane >> 3;
    const int li = lane & 7;
    const int base = blockIdx.x * 128;

    const uint32_t sAhi_u = smem_u32(sA_hi);
    const uint32_t sAlo_u = smem_u32(sA_lo);
    const uint32_t sWhi_u = smem_u32(sW_hi);
    const uint32_t sWlo_u = smem_u32(sW_lo);

    // ---- Stage A: pure 16B copies from pre-split gather output ----
    constexpr int CH = K_IN / 8;  // 16B chunks of data per row
    for (int idx = tid; idx < 128 * CH; idx += 128) {
        int row = idx / CH, cch = idx % CH;
        int gn = base + row;
        uint4 vh = make_uint4(0, 0, 0, 0), vl = vh;
        if (gn < NN) {
            vh = *(const uint4*)(Ah + (size_t)gn * K_IN + cch * 8);
            vl = *(const uint4*)(Al + (size_t)gn * K_IN + cch * 8);
        }
        uint32_t o = rb(row) ^ (uint32_t)(cch * 16);
        *(uint4*)(sA_hi + o) = vh;
        *(uint4*)(sA_lo + o) = vl;
    }
    // ---- Stage W1 transposed: sW[n][k] ----
    for (int i = tid; i < 64 * 32; i += 128) {
        int n = i >> 5, c2 = i & 31;
        int k0 = c2 * 2;
        float w0  = (k0     < w1Rows) ? W1[(k0    ) * 64 + n] : 0.0f;
        float w1v = (k0 + 1 < w1Rows) ? W1[(k0 + 1) * 64 + n] : 0.0f;
        uint32_t lo, hi = packsplit(w0, w1v, lo);
        uint32_t o = rb(n) ^ (uint32_t)(k0 * 2);
        *(uint32_t*)(sW_hi + o) = hi;
        *(uint32_t*)(sW_lo + o) = lo;
    }
    __syncthreads();

    // ---- Precompute ldmatrix lane bases (one XOR per load afterwards) ----
    uint32_t aBH[2], aBL[2];
#pragma unroll
    for (int m = 0; m < 2; m++) {
        int rowA = warp * 32 + m * 16 + li + (g & 1) * 8;
        uint32_t ka = (uint32_t)((g >> 1) * 16);
        uint32_t r = rb(rowA) ^ ka;
        aBH[m] = sAhi_u + r;
        aBL[m] = sAlo_u + r;
    }
    uint32_t bBH[4], bBL[4];
#pragma unroll
    for (int p = 0; p < 4; p++) {
        int rowB = p * 16 + ((g >> 1) & 1) * 8 + li;
        uint32_t kb = (uint32_t)((g & 1) * 16);
        uint32_t r = rb(rowB) ^ kb;
        bBH[p] = sWhi_u + r;
        bBL[p] = sWlo_u + r;
    }

    float c[2][8][4];
#pragma unroll
    for (int m = 0; m < 2; m++)
#pragma unroll
        for (int n = 0; n < 8; n++)
#pragma unroll
            for (int j = 0; j < 4; j++) c[m][n][j] = 0.0f;

    // ---- GEMM1 ----
    do_gemm<K_IN / 16>(c, aBH, aBL, bBH, bBL);

    // ---- Epilogue 1: h = relu(C+b1) -> re-split into A tiles ----
#pragma unroll
    for (int m = 0; m < 2; m++) {
        int r0 = warp * 32 + m * 16 + qr;
        uint32_t rb0 = rb(r0), rb1 = rb(r0 + 8);
#pragma unroll
        for (int nt = 0; nt < 8; nt++) {
            uint32_t cb = (uint32_t)(nt * 16 + qc * 4);
            int col = nt * 8 + qc * 2;
            float bv0 = __ldg(b1 + col), bv1 = __ldg(b1 + col + 1);
            float v0 = fmaxf(c[m][nt][0] + bv0, 0.0f);
            float v1 = fmaxf(c[m][nt][1] + bv1, 0.0f);
            float v2 = fmaxf(c[m][nt][2] + bv0, 0.0f);
            float v3 = fmaxf(c[m][nt][3] + bv1, 0.0f);
            uint32_t lo, hi;
            hi = packsplit(v0, v1, lo);
            *(uint32_t*)(sA_hi + (rb0 ^ cb)) = hi;
            *(uint32_t*)(sA_lo + (rb0 ^ cb)) = lo;
            hi = packsplit(v2, v3, lo);
            *(uint32_t*)(sA_hi + (rb1 ^ cb)) = hi;
            *(uint32_t*)(sA_lo + (rb1 ^ cb)) = lo;
        }
    }
    __syncthreads();

    // ---- Restage W2 ----
    for (int i = tid; i < 64 * 32; i += 128) {
        int n = i >> 5, c2 = i & 31;
        int k0 = c2 * 2;
        uint32_t lo, hi = packsplit(W2[k0 * 64 + n], W2[(k0 + 1) * 64 + n], lo);
        uint32_t o = rb(n) ^ (uint32_t)(k0 * 2);
        *(uint32_t*)(sW_hi + o) = hi;
        *(uint32_t*)(sW_lo + o) = lo;
    }
    __syncthreads();

#pragma unroll
    for (int m = 0; m < 2; m++)
#pragma unroll
        for (int n = 0; n < 8; n++)
#pragma unroll
            for (int j = 0; j < 4; j++) c[m][n][j] = 0.0f;

    // ---- GEMM2 ----
    do_gemm<4>(c, aBH, aBL, bBH, bBL);

    // ---- Epilogue 2 ----
    if (!POOL) {
#pragma unroll
        for (int m = 0; m < 2; m++) {
            int r0 = warp * 32 + m * 16 + qr;
            int gn0 = base + r0, gn1 = gn0 + 8;
#pragma unroll
            for (int nt = 0; nt < 8; nt++) {
                int col = nt * 8 + qc * 2;
                float bv0 = __ldg(b2 + col), bv1 = __ldg(b2 + col + 1);
                if (gn0 < NN)
                    *(float2*)(out + (size_t)gn0 * 64 + col) =
                        make_float2(c[m][nt][0] + bv0, c[m][nt][1] + bv1);
                if (gn1 < NN)
                    *(float2*)(out + (size_t)gn1 * 64 + col) =
                        make_float2(c[m][nt][2] + bv0, c[m][nt][3] + bv1);
            }
        }
    } else {
#pragma unroll
        for (int m = 0; m < 2; m++) {
            int r0 = warp * 32 + m * 16 + qr;
            int gn0 = base + r0, gn1 = gn0 + 8;
            float s0 = 0.0f, s1 = 0.0f;
#pragma unroll
            for (int nt = 0; nt < 8; nt++) {
                int col = nt * 8 + qc * 2;
                float bv0 = __ldg(b2 + col), bv1 = __ldg(b2 + col + 1);
                float w0 = __ldg(wout + col), w1 = __ldg(wout + col + 1);
                s0 += (c[m][nt][0] + bv0) * w0 + (c[m][nt][1] + bv1) * w1;
                s1 += (c[m][nt][2] + bv0) * w0 + (c[m][nt][3] + bv1) * w1;
            }
            s0 += __shfl_xor_sync(0xFFFFFFFF, s0, 1);
            s0 += __shfl_xor_sync(0xFFFFFFFF, s0, 2);
            s1 += __shfl_xor_sync(0xFFFFFFFF, s1, 1);
            s1 += __shfl_xor_sync(0xFFFFFFFF, s1, 2);
            if (qc == 0) {
                if (gn0 < NN) atomicAdd(&outp[__ldg(batch + gn0)], s0);
                if (gn1 < NN) atomicAdd(&outp[__ldg(batch + gn1)], s1);
            }
        }
    }
}

// ---------------------------------------------------------------------------
extern "C" void kernel_launch(void* const* d_in, const int* in_sizes, int n_in,
                              void* d_out, int out_size) {
    const float* x     = (const float*)d_in[0];
    const int*   ei    = (const int*)d_in[1];   // [2, E]
    const int*   batch = (const int*)d_in[2];
    const float* eps0  = (const float*)d_in[3];
    const float* w1_0  = (const float*)d_in[4];
    const float* b1_0  = (const float*)d_in[5];
    const float* w2_0  = (const float*)d_in[6];
    const float* b2_0  = (const float*)d_in[7];
    const float* eps_r = (const float*)d_in[8];
    const float* w1_r  = (const float*)d_in[9];
    const float* b1_r  = (const float*)d_in[10];
    const float* w2_r  = (const float*)d_in[11];
    const float* b2_r  = (const float*)d_in[12];
    const float* w_out = (const float*)d_in[13];
    const float* b_out = (const float*)d_in[14];

    const int* src = ei;
    const int* dst = ei + EE;

    float *xpad, *hbuf;
    uint16_t *agh, *agl;
    int *deg, *off, *cur, *edge, *part, *bsum;
    cudaGetSymbolAddress((void**)&xpad, g_xpad);
    cudaGetSymbolAddress((void**)&hbuf, g_hbuf);
    cudaGetSymbolAddress((void**)&agh,  g_aggh);
    cudaGetSymbolAddress((void**)&agl,  g_aggl);
    cudaGetSymbolAddress((void**)&deg,  g_deg);
    cudaGetSymbolAddress((void**)&off,  g_off);
    cudaGetSymbolAddress((void**)&cur,  g_cur);
    cudaGetSymbolAddress((void**)&edge, g_edge);
    cudaGetSymbolAddress((void**)&part, g_part);
    cudaGetSymbolAddress((void**)&bsum, g_bsum);

    float* outp = (float*)d_out;
    const int TB = 256;
    const int mlp_grid = (NN + 127) / 128;

    // ---- CSR build (one-time) + prep ----
    pad_init_kernel<<<(NN * 32 + TB - 1) / TB, TB>>>(x, xpad, deg);
    count_deg_kernel<<<(EE + TB - 1) / TB, TB>>>(dst, deg);
    scan_block_kernel<<<98, 1024>>>(deg, part, bsum);
    scan_add_kernel<<<98, 1024>>>(part, bsum, off, cur);
    place_kernel<<<(EE + TB - 1) / TB, TB>>>(src, dst, cur, edge);
    out_init_kernel<<<1, 128>>>(outp, b_out);

    // ---- Layer 0 (K=32) ----
    gather_kernel<32><<<(NN * 8 + 255) / 256, 256>>>(xpad, agh, agl, off, deg, edge, eps0);
    fused_mlp_kernel<32, false><<<mlp_grid, 128>>>(agh, agl, w1_0, b1_0, w2_0, b2_0, 30,
                                                   hbuf, nullptr, nullptr, nullptr);
    // ---- Layers 1..2 ----
    for (int i = 0; i < 2; i++) {
        gather_kernel<64><<<(NN * 16 + 255) / 256, 256>>>(hbuf, agh, agl, off, deg, edge, eps_r + i);
        fused_mlp_kernel<64, false><<<mlp_grid, 128>>>(agh, agl, w1_r + i * 4096, b1_r + i * 64,
                                                       w2_r + i * 4096, b2_r + i * 64, 64,
                                                       hbuf, nullptr, nullptr, nullptr);
    }
    // ---- Layer 3 (fused pool) ----
    gather_kernel<64><<<(NN * 16 + 255) / 256, 256>>>(hbuf, agh, agl, off, deg, edge, eps_r + 2);
    fused_mlp_kernel<64, true><<<mlp_grid, 128>>>(agh, agl, w1_r + 8192, b1_r + 128,
                                                  w2_r + 8192, b2_r + 128, 64,
                                                  nullptr, batch, w_out, outp);
}

// round 9
// speedup vs baseline: 1.7406x; 1.0723x over previous
#include <cuda_runtime.h>
#include <cuda_bf16.h>
#include <cuda_fp16.h>
#include <cstdint>
#include <cstring>

#define NN 100000
#define EE 1200000
#define GG 128

// Scratch (device globals: no allocation anywhere)
__device__ __align__(16) __half g_xpad[NN * 32];
__device__ __align__(16) __half g_hbuf[NN * 64];
__device__ __align__(16) uint16_t g_aggh[NN * 64];
__device__ __align__(16) uint16_t g_aggl[NN * 64];
__device__ int   g_deg[NN];
__device__ int   g_off[NN];
__device__ int   g_cur[NN];
__device__ int   g_edge[EE];
__device__ int   g_part[100352];   // 98*1024 block-scanned partials
__device__ int   g_bsum[128];

// ---------------------------------------------------------------------------
// Helpers
// ---------------------------------------------------------------------------
__device__ __forceinline__ uint32_t smem_u32(const void* p) {
    uint32_t a;
    asm("{ .reg .u64 t; cvta.to.shared.u64 t, %1; cvt.u32.u64 %0, t; }"
        : "=r"(a) : "l"(p));
    return a;
}

// Swizzled row base: swz(row*128 + kb) == rb(row) ^ kb  for kb < 128 (no carry)
__device__ __forceinline__ uint32_t rb(int row) {
    return (uint32_t)(row * 128) ^ (((uint32_t)row & 7u) << 4);
}

__device__ __forceinline__ void ldm_x4(uint32_t r[4], uint32_t addr) {
    asm volatile("ldmatrix.sync.aligned.m8n8.x4.shared.b16 {%0,%1,%2,%3}, [%4];"
                 : "=r"(r[0]), "=r"(r[1]), "=r"(r[2]), "=r"(r[3]) : "r"(addr));
}

__device__ __forceinline__ void mma_bf16(float c[4], const uint32_t a[4],
                                         uint32_t b0, uint32_t b1) {
    asm volatile(
        "mma.sync.aligned.m16n8k16.row.col.f32.bf16.bf16.f32 "
        "{%0,%1,%2,%3}, {%4,%5,%6,%7}, {%8,%9}, {%0,%1,%2,%3};"
        : "+f"(c[0]), "+f"(c[1]), "+f"(c[2]), "+f"(c[3])
        : "r"(a[0]), "r"(a[1]), "r"(a[2]), "r"(a[3]), "r"(b0), "r"(b1));
}

__device__ __forceinline__ void split_bf16(float v, __nv_bfloat16& h, __nv_bfloat16& l) {
    h = __float2bfloat16_rn(v);
    l = __float2bfloat16_rn(v - __bfloat162float(h));
}

// Split+pack two floats: returns hi-pair (bf16x2 bits), writes lo-pair.
__device__ __forceinline__ uint32_t packsplit(float a, float b, uint32_t& lopack) {
    __nv_bfloat16 ha, la, hb, lb;
    split_bf16(a, ha, la);
    split_bf16(b, hb, lb);
    uint16_t ua, ub, va, vb;
    memcpy(&ua, &ha, 2); memcpy(&ub, &hb, 2);
    memcpy(&va, &la, 2); memcpy(&vb, &lb, 2);
    lopack = (uint32_t)va | ((uint32_t)vb << 16);
    return (uint32_t)ua | ((uint32_t)ub << 16);
}

// ---------------------------------------------------------------------------
// CSR build + prep
// ---------------------------------------------------------------------------
__global__ void pad_init_kernel(const float* __restrict__ x,
                                __half* __restrict__ xpad,
                                int* __restrict__ deg) {
    int i = blockIdx.x * blockDim.x + threadIdx.x;
    if (i >= NN * 32) return;
    int n = i >> 5, c = i & 31;
    xpad[i] = __float2half(c < 30 ? x[n * 30 + c] : 0.0f);
    if (c == 0) deg[n] = 0;
}

__global__ void count_deg_kernel(const int* __restrict__ dst, int* __restrict__ deg,
                                 float* __restrict__ outp,
                                 const float* __restrict__ b_out) {
    int e = blockIdx.x * blockDim.x + threadIdx.x;
    if (e < EE) atomicAdd(&deg[__ldg(dst + e)], 1);
    if (blockIdx.x == 0 && threadIdx.x < GG) outp[threadIdx.x] = b_out[0];
}

__global__ void scan_block_kernel(const int* __restrict__ deg,
                                  int* __restrict__ part, int* __restrict__ bsum) {
    __shared__ int sh[1024];
    int tid = threadIdx.x;
    int gid = blockIdx.x * 1024 + tid;
    int v = (gid < NN) ? deg[gid] : 0;
    sh[tid] = v;
    __syncthreads();
    for (int ofs = 1; ofs < 1024; ofs <<= 1) {
        int t = 0;
        if (tid >= ofs) t = sh[tid - ofs];
        __syncthreads();
        if (tid >= ofs) sh[tid] += t;
        __syncthreads();
    }
    part[gid] = sh[tid] - v;   // exclusive
    if (tid == 1023) bsum[blockIdx.x] = sh[1023];
}

__global__ void scan_add_kernel(const int* __restrict__ part,
                                const int* __restrict__ bsum,
                                int* __restrict__ off, int* __restrict__ cur) {
    __shared__ int sh[128];
    int tid = threadIdx.x;
    if (tid < 128) {
        int v = (tid < 98) ? bsum[tid] : 0;
        sh[tid] = v;
    }
    __syncthreads();
    if (tid < 128) {
        for (int ofs = 1; ofs < 128; ofs <<= 1) {
            int t = 0;
            if (tid >= ofs) t = sh[tid - ofs];
            __syncthreads();
            if (tid >= ofs) sh[tid] += t;
            __syncthreads();
        }
    } else {
        for (int ofs = 1; ofs < 128; ofs <<= 1) { __syncthreads(); __syncthreads(); }
    }
    __syncthreads();
    int gid = blockIdx.x * 1024 + tid;
    if (gid >= NN) return;
    int blk_excl = (blockIdx.x == 0) ? 0 : sh[blockIdx.x - 1];
    int o = part[gid] + blk_excl;
    off[gid] = o;
    cur[gid] = o;
}

__global__ void place_kernel(const int* __restrict__ src, const int* __restrict__ dst,
                             int* __restrict__ cur, int* __restrict__ edge) {
    int e = blockIdx.x * blockDim.x + threadIdx.x;
    if (e >= EE) return;
    int d = __ldg(dst + e);
    int p = atomicAdd(&cur[d], 1);
    edge[p] = __ldg(src + e);
}

// ---------------------------------------------------------------------------
// Gather: acc = (1+eps)*h[n] + sum h[src_e] over fp16 rows (128B for K=64).
// K/8 lanes per node, 16B (8 halfs) per lane. fp32 accumulate; output is the
// bf16 hi/lo split the MLP consumes directly.
// ---------------------------------------------------------------------------
template <int K>
__global__ __launch_bounds__(256) void gather_kernel(
    const __half* __restrict__ hin,
    uint16_t* __restrict__ agh, uint16_t* __restrict__ agl,
    const int* __restrict__ off, const int* __restrict__ deg,
    const int* __restrict__ edge, const float* __restrict__ eps) {
    constexpr int L = K / 8;             // lanes per node (16B each)
    const int tid = blockIdx.x * 256 + threadIdx.x;
    const int gn = tid / L;
    const int sub = tid % L;
    if (gn >= NN) return;

    float acc[8];
    const float s = 1.0f + __ldg(eps);
    {
        uint4 u = *(const uint4*)(hin + (size_t)gn * K + sub * 8);
        const __half2* hp = (const __half2*)&u;
#pragma unroll
        for (int j = 0; j < 4; j++) {
            float2 f = __half22float2(hp[j]);
            acc[j * 2 + 0] = s * f.x;
            acc[j * 2 + 1] = s * f.y;
        }
    }

    const int e0 = __ldg(off + gn);
    const int dg = __ldg(deg + gn);
    int e = 0;
    for (; e + 2 <= dg; e += 2) {
        int sn0 = __ldg(edge + e0 + e);
        int sn1 = __ldg(edge + e0 + e + 1);
        uint4 ua = *(const uint4*)(hin + (size_t)sn0 * K + sub * 8);
        uint4 ub = *(const uint4*)(hin + (size_t)sn1 * K + sub * 8);
        const __half2* pa = (const __half2*)&ua;
        const __half2* pb = (const __half2*)&ub;
#pragma unroll
        for (int j = 0; j < 4; j++) {
            float2 fa = __half22float2(pa[j]);
            float2 fb = __half22float2(pb[j]);
            acc[j * 2 + 0] += fa.x + fb.x;
            acc[j * 2 + 1] += fa.y + fb.y;
        }
    }
    if (e < dg) {
        int sn0 = __ldg(edge + e0 + e);
        uint4 ua = *(const uint4*)(hin + (size_t)sn0 * K + sub * 8);
        const __half2* pa = (const __half2*)&ua;
#pragma unroll
        for (int j = 0; j < 4; j++) {
            float2 fa = __half22float2(pa[j]);
            acc[j * 2 + 0] += fa.x;
            acc[j * 2 + 1] += fa.y;
        }
    }

    uint4 hv, lv;
    hv.x = packsplit(acc[0], acc[1], lv.x);
    hv.y = packsplit(acc[2], acc[3], lv.y);
    hv.z = packsplit(acc[4], acc[5], lv.z);
    hv.w = packsplit(acc[6], acc[7], lv.w);
    *(uint4*)(agh + (size_t)gn * K + sub * 8) = hv;
    *(uint4*)(agl + (size_t)gn * K + sub * 8) = lv;
}

// ---------------------------------------------------------------------------
// GEMM core: C[2][8][4] += A(smem swz, hi/lo) @ W(smem swz, hi/lo), 3 terms.
// ---------------------------------------------------------------------------
template <int KS>
__device__ __forceinline__ void do_gemm(float c[2][8][4],
                                        const uint32_t aBH[2], const uint32_t aBL[2],
                                        const uint32_t bBH[4], const uint32_t bBL[4]) {
#pragma unroll
    for (int ks = 0; ks < KS; ks++) {
        const uint32_t kx = ks * 32;
        uint32_t aH[2][4], aL[2][4];
#pragma unroll
        for (int m = 0; m < 2; m++) {
            ldm_x4(aH[m], aBH[m] ^ kx);
            ldm_x4(aL[m], aBL[m] ^ kx);
        }
#pragma unroll
        for (int p = 0; p < 4; p++) {
            uint32_t bh[4], bl[4];
            ldm_x4(bh, bBH[p] ^ kx);
            ldm_x4(bl, bBL[p] ^ kx);
#pragma unroll
            for (int s = 0; s < 2; s++) {
                const int nt = 2 * p + s;
#pragma unroll
                for (int m = 0; m < 2; m++) {
                    mma_bf16(c[m][nt], aH[m], bh[s * 2], bh[s * 2 + 1]);
                    mma_bf16(c[m][nt], aH[m], bl[s * 2], bl[s * 2 + 1]);
                    mma_bf16(c[m][nt], aL[m], bh[s * 2], bh[s * 2 + 1]);
                }
            }
        }
    }
}

// ---------------------------------------------------------------------------
// Fused GIN MLP: out = relu(A@W1+b1)@W2+b2 per 128-node tile.
// A arrives pre-split (hi/lo bf16). Output fp16. POOL folds h.w_out.
// ---------------------------------------------------------------------------
template <int K_IN, bool POOL>
__global__ __launch_bounds__(128) void fused_mlp_kernel(
    const uint16_t* __restrict__ Ah, const uint16_t* __restrict__ Al,
    const float* __restrict__ W1, const float* __restrict__ b1,
    const float* __restrict__ W2, const float* __restrict__ b2, int w1Rows,
    __half* __restrict__ out,
    const int* __restrict__ batch,
    const float* __restrict__ wout, float* __restrict__ outp) {
    __shared__ __align__(128) char sA_hi[128 * 128];  // 16KB
    __shared__ __align__(128) char sA_lo[128 * 128];  // 16KB
    __shared__ __align__(128) char sW_hi[64 * 128];   // 8KB
    __shared__ __align__(128) char sW_lo[64 * 128];   // 8KB

    const int tid  = threadIdx.x;
    const int warp = tid >> 5;
    const int lane = tid & 31;
    const int qr = lane >> 2;
    const int qc = lane & 3;
    const int g  = lane >> 3;
    const int li = lane & 7;
    const int base = blockIdx.x * 128;

    const uint32_t sAhi_u = smem_u32(sA_hi);
    const uint32_t sAlo_u = smem_u32(sA_lo);
    const uint32_t sWhi_u = smem_u32(sW_hi);
    const uint32_t sWlo_u = smem_u32(sW_lo);

    // ---- Stage A: pure 16B copies from pre-split gather output ----
    constexpr int CH = K_IN / 8;  // 16B chunks of data per row
    for (int idx = tid; idx < 128 * CH; idx += 128) {
        int row = idx / CH, cch = idx % CH;
        int gn = base + row;
        uint4 vh = make_uint4(0, 0, 0, 0), vl = vh;
        if (gn < NN) {
            vh = *(const uint4*)(Ah + (size_t)gn * K_IN + cch * 8);
            vl = *(const uint4*)(Al + (size_t)gn * K_IN + cch * 8);
        }
        uint32_t o = rb(row) ^ (uint32_t)(cch * 16);
        *(uint4*)(sA_hi + o) = vh;
        *(uint4*)(sA_lo + o) = vl;
    }
    // ---- Stage W1 transposed: sW[n][k] ----
    for (int i = tid; i < 64 * 32; i += 128) {
        int n = i >> 5, c2 = i & 31;
        int k0 = c2 * 2;
        float w0  = (k0     < w1Rows) ? W1[(k0    ) * 64 + n] : 0.0f;
        float w1v = (k0 + 1 < w1Rows) ? W1[(k0 + 1) * 64 + n] : 0.0f;
        uint32_t lo, hi = packsplit(w0, w1v, lo);
        uint32_t o = rb(n) ^ (uint32_t)(k0 * 2);
        *(uint32_t*)(sW_hi + o) = hi;
        *(uint32_t*)(sW_lo + o) = lo;
    }
    __syncthreads();

    // ---- Precompute ldmatrix lane bases ----
    uint32_t aBH[2], aBL[2];
#pragma unroll
    for (int m = 0; m < 2; m++) {
        int rowA = warp * 32 + m * 16 + li + (g & 1) * 8;
        uint32_t ka = (uint32_t)((g >> 1) * 16);
        uint32_t r = rb(rowA) ^ ka;
        aBH[m] = sAhi_u + r;
        aBL[m] = sAlo_u + r;
    }
    uint32_t bBH[4], bBL[4];
#pragma unroll
    for (int p = 0; p < 4; p++) {
        int rowB = p * 16 + ((g >> 1) & 1) * 8 + li;
        uint32_t kb = (uint32_t)((g & 1) * 16);
        uint32_t r = rb(rowB) ^ kb;
        bBH[p] = sWhi_u + r;
        bBL[p] = sWlo_u + r;
    }

    float c[2][8][4];
#pragma unroll
    for (int m = 0; m < 2; m++)
#pragma unroll
        for (int n = 0; n < 8; n++)
#pragma unroll
            for (int j = 0; j < 4; j++) c[m][n][j] = 0.0f;

    // ---- GEMM1 ----
    do_gemm<K_IN / 16>(c, aBH, aBL, bBH, bBL);

    // ---- Epilogue 1: h = relu(C+b1) -> re-split into A tiles ----
#pragma unroll
    for (int m = 0; m < 2; m++) {
        int r0 = warp * 32 + m * 16 + qr;
        uint32_t rb0 = rb(r0), rb1 = rb(r0 + 8);
#pragma unroll
        for (int nt = 0; nt < 8; nt++) {
            uint32_t cb = (uint32_t)(nt * 16 + qc * 4);
            int col = nt * 8 + qc * 2;
            float bv0 = __ldg(b1 + col), bv1 = __ldg(b1 + col + 1);
            float v0 = fmaxf(c[m][nt][0] + bv0, 0.0f);
            float v1 = fmaxf(c[m][nt][1] + bv1, 0.0f);
            float v2 = fmaxf(c[m][nt][2] + bv0, 0.0f);
            float v3 = fmaxf(c[m][nt][3] + bv1, 0.0f);
            uint32_t lo, hi;
            hi = packsplit(v0, v1, lo);
            *(uint32_t*)(sA_hi + (rb0 ^ cb)) = hi;
            *(uint32_t*)(sA_lo + (rb0 ^ cb)) = lo;
            hi = packsplit(v2, v3, lo);
            *(uint32_t*)(sA_hi + (rb1 ^ cb)) = hi;
            *(uint32_t*)(sA_lo + (rb1 ^ cb)) = lo;
        }
    }
    __syncthreads();

    // ---- Restage W2 ----
    for (int i = tid; i < 64 * 32; i += 128) {
        int n = i >> 5, c2 = i & 31;
        int k0 = c2 * 2;
        uint32_t lo, hi = packsplit(W2[k0 * 64 + n], W2[(k0 + 1) * 64 + n], lo);
        uint32_t o = rb(n) ^ (uint32_t)(k0 * 2);
        *(uint32_t*)(sW_hi + o) = hi;
        *(uint32_t*)(sW_lo + o) = lo;
    }
    __syncthreads();

#pragma unroll
    for (int m = 0; m < 2; m++)
#pragma unroll
        for (int n = 0; n < 8; n++)
#pragma unroll
            for (int j = 0; j < 4; j++) c[m][n][j] = 0.0f;

    // ---- GEMM2 ----
    do_gemm<4>(c, aBH, aBL, bBH, bBL);

    // ---- Epilogue 2 ----
    if (!POOL) {
#pragma unroll
        for (int m = 0; m < 2; m++) {
            int r0 = warp * 32 + m * 16 + qr;
            int gn0 = base + r0, gn1 = gn0 + 8;
#pragma unroll
            for (int nt = 0; nt < 8; nt++) {
                int col = nt * 8 + qc * 2;
                float bv0 = __ldg(b2 + col), bv1 = __ldg(b2 + col + 1);
                if (gn0 < NN)
                    *(__half2*)(out + (size_t)gn0 * 64 + col) =
                        __floats2half2_rn(c[m][nt][0] + bv0, c[m][nt][1] + bv1);
                if (gn1 < NN)
                    *(__half2*)(out + (size_t)gn1 * 64 + col) =
                        __floats2half2_rn(c[m][nt][2] + bv0, c[m][nt][3] + bv1);
            }
        }
    } else {
#pragma unroll
        for (int m = 0; m < 2; m++) {
            int r0 = warp * 32 + m * 16 + qr;
            int gn0 = base + r0, gn1 = gn0 + 8;
            float s0 = 0.0f, s1 = 0.0f;
#pragma unroll
            for (int nt = 0; nt < 8; nt++) {
                int col = nt * 8 + qc * 2;
                float bv0 = __ldg(b2 + col), bv1 = __ldg(b2 + col + 1);
                float w0 = __ldg(wout + col), w1 = __ldg(wout + col + 1);
                s0 += (c[m][nt][0] + bv0) * w0 + (c[m][nt][1] + bv1) * w1;
                s1 += (c[m][nt][2] + bv0) * w0 + (c[m][nt][3] + bv1) * w1;
            }
            s0 += __shfl_xor_sync(0xFFFFFFFF, s0, 1);
            s0 += __shfl_xor_sync(0xFFFFFFFF, s0, 2);
            s1 += __shfl_xor_sync(0xFFFFFFFF, s1, 1);
            s1 += __shfl_xor_sync(0xFFFFFFFF, s1, 2);
            if (qc == 0) {
                if (gn0 < NN) atomicAdd(&outp[__ldg(batch + gn0)], s0);
                if (gn1 < NN) atomicAdd(&outp[__ldg(batch + gn1)], s1);
            }
        }
    }
}

// ---------------------------------------------------------------------------
extern "C" void kernel_launch(void* const* d_in, const int* in_sizes, int n_in,
                              void* d_out, int out_size) {
    const float* x     = (const float*)d_in[0];
    const int*   ei    = (const int*)d_in[1];   // [2, E]
    const int*   batch = (const int*)d_in[2];
    const float* eps0  = (const float*)d_in[3];
    const float* w1_0  = (const float*)d_in[4];
    const float* b1_0  = (const float*)d_in[5];
    const float* w2_0  = (const float*)d_in[6];
    const float* b2_0  = (const float*)d_in[7];
    const float* eps_r = (const float*)d_in[8];
    const float* w1_r  = (const float*)d_in[9];
    const float* b1_r  = (const float*)d_in[10];
    const float* w2_r  = (const float*)d_in[11];
    const float* b2_r  = (const float*)d_in[12];
    const float* w_out = (const float*)d_in[13];
    const float* b_out = (const float*)d_in[14];

    const int* src = ei;
    const int* dst = ei + EE;

    __half *xpad, *hbuf;
    uint16_t *agh, *agl;
    int *deg, *off, *cur, *edge, *part, *bsum;
    cudaGetSymbolAddress((void**)&xpad, g_xpad);
    cudaGetSymbolAddress((void**)&hbuf, g_hbuf);
    cudaGetSymbolAddress((void**)&agh,  g_aggh);
    cudaGetSymbolAddress((void**)&agl,  g_aggl);
    cudaGetSymbolAddress((void**)&deg,  g_deg);
    cudaGetSymbolAddress((void**)&off,  g_off);
    cudaGetSymbolAddress((void**)&cur,  g_cur);
    cudaGetSymbolAddress((void**)&edge, g_edge);
    cudaGetSymbolAddress((void**)&part, g_part);
    cudaGetSymbolAddress((void**)&bsum, g_bsum);

    float* outp = (float*)d_out;
    const int TB = 256;
    const int mlp_grid = (NN + 127) / 128;

    // ---- CSR build (one-time) + prep: 5 launches ----
    pad_init_kernel<<<(NN * 32 + TB - 1) / TB, TB>>>(x, xpad, deg);
    count_deg_kernel<<<(EE + TB - 1) / TB, TB>>>(dst, deg, outp, b_out);
    scan_block_kernel<<<98, 1024>>>(deg, part, bsum);
    scan_add_kernel<<<98, 1024>>>(part, bsum, off, cur);
    place_kernel<<<(EE + TB - 1) / TB, TB>>>(src, dst, cur, edge);

    // ---- Layer 0 (K=32) ----
    gather_kernel<32><<<(NN * 4 + 255) / 256, 256>>>(xpad, agh, agl, off, deg, edge, eps0);
    fused_mlp_kernel<32, false><<<mlp_grid, 128>>>(agh, agl, w1_0, b1_0, w2_0, b2_0, 30,
                                                   hbuf, nullptr, nullptr, nullptr);
    // ---- Layers 1..2 ----
    for (int i = 0; i < 2; i++) {
        gather_kernel<64><<<(NN * 8 + 255) / 256, 256>>>(hbuf, agh, agl, off, deg, edge, eps_r + i);
        fused_mlp_kernel<64, false><<<mlp_grid, 128>>>(agh, agl, w1_r + i * 4096, b1_r + i * 64,
                                                       w2_r + i * 4096, b2_r + i * 64, 64,
                                                       hbuf, nullptr, nullptr, nullptr);
    }
    // ---- Layer 3 (fused pool) ----
    gather_kernel<64><<<(NN * 8 + 255) / 256, 256>>>(hbuf, agh, agl, off, deg, edge, eps_r + 2);
    fused_mlp_kernel<64, true><<<mlp_grid, 128>>>(agh, agl, w1_r + 8192, b1_r + 128,
                                                  w2_r + 8192, b2_r + 128, 64,
                                                  nullptr, batch, w_out, outp);
}

// round 10
// speedup vs baseline: 1.8697x; 1.0742x over previous
#include <cuda_runtime.h>
#include <cuda_bf16.h>
#include <cuda_fp16.h>
#include <cstdint>
#include <cstring>

#define NN 100000
#define EE 1200000
#define GG 128

// Scratch (device globals: no allocation anywhere)
__device__ __align__(16) __half g_xpad[NN * 32];
__device__ __align__(16) __half g_hbuf[NN * 64];
__device__ __align__(16) uint16_t g_aggh[NN * 64];
__device__ int   g_deg[NN];
__device__ int   g_off[NN];
__device__ int   g_cur[NN];
__device__ int   g_edge[EE];
__device__ int   g_part[100352];   // 98*1024 block-scanned partials
__device__ int   g_bsum[128];

// ---------------------------------------------------------------------------
// Helpers
// ---------------------------------------------------------------------------
__device__ __forceinline__ uint32_t smem_u32(const void* p) {
    uint32_t a;
    asm("{ .reg .u64 t; cvta.to.shared.u64 t, %1; cvt.u32.u64 %0, t; }"
        : "=r"(a) : "l"(p));
    return a;
}

// Swizzled row base: swz(row*128 + kb) == rb(row) ^ kb  for kb < 128 (no carry)
__device__ __forceinline__ uint32_t rb(int row) {
    return (uint32_t)(row * 128) ^ (((uint32_t)row & 7u) << 4);
}

__device__ __forceinline__ void ldm_x4(uint32_t r[4], uint32_t addr) {
    asm volatile("ldmatrix.sync.aligned.m8n8.x4.shared.b16 {%0,%1,%2,%3}, [%4];"
                 : "=r"(r[0]), "=r"(r[1]), "=r"(r[2]), "=r"(r[3]) : "r"(addr));
}

__device__ __forceinline__ void mma_bf16(float c[4], const uint32_t a[4],
                                         uint32_t b0, uint32_t b1) {
    asm volatile(
        "mma.sync.aligned.m16n8k16.row.col.f32.bf16.bf16.f32 "
        "{%0,%1,%2,%3}, {%4,%5,%6,%7}, {%8,%9}, {%0,%1,%2,%3};"
        : "+f"(c[0]), "+f"(c[1]), "+f"(c[2]), "+f"(c[3])
        : "r"(a[0]), "r"(a[1]), "r"(a[2]), "r"(a[3]), "r"(b0), "r"(b1));
}

__device__ __forceinline__ void split_bf16(float v, __nv_bfloat16& h, __nv_bfloat16& l) {
    h = __float2bfloat16_rn(v);
    l = __float2bfloat16_rn(v - __bfloat162float(h));
}

// Split+pack two floats: returns hi-pair (bf16x2 bits), writes lo-pair.
__device__ __forceinline__ uint32_t packsplit(float a, float b, uint32_t& lopack) {
    __nv_bfloat16 ha, la, hb, lb;
    split_bf16(a, ha, la);
    split_bf16(b, hb, lb);
    uint16_t ua, ub, va, vb;
    memcpy(&ua, &ha, 2); memcpy(&ub, &hb, 2);
    memcpy(&va, &la, 2); memcpy(&vb, &lb, 2);
    lopack = (uint32_t)va | ((uint32_t)vb << 16);
    return (uint32_t)ua | ((uint32_t)ub << 16);
}

// Pack two floats as plain bf16x2.
__device__ __forceinline__ uint32_t packbf2(float a, float b) {
    __nv_bfloat162 p = __floats2bfloat162_rn(a, b);
    uint32_t u;
    memcpy(&u, &p, 4);
    return u;
}

// ---------------------------------------------------------------------------
// CSR build + prep
// ---------------------------------------------------------------------------
__global__ void pad_init_kernel(const float* __restrict__ x,
                                __half* __restrict__ xpad,
                                int* __restrict__ deg) {
    int i = blockIdx.x * blockDim.x + threadIdx.x;
    if (i >= NN * 32) return;
    int n = i >> 5, c = i & 31;
    xpad[i] = __float2half(c < 30 ? x[n * 30 + c] : 0.0f);
    if (c == 0) deg[n] = 0;
}

__global__ void count_deg_kernel(const int* __restrict__ dst, int* __restrict__ deg,
                                 float* __restrict__ outp,
                                 const float* __restrict__ b_out) {
    int e = blockIdx.x * blockDim.x + threadIdx.x;
    if (e < EE) atomicAdd(&deg[__ldg(dst + e)], 1);
    if (blockIdx.x == 0 && threadIdx.x < GG) outp[threadIdx.x] = b_out[0];
}

__global__ void scan_block_kernel(const int* __restrict__ deg,
                                  int* __restrict__ part, int* __restrict__ bsum) {
    __shared__ int sh[1024];
    int tid = threadIdx.x;
    int gid = blockIdx.x * 1024 + tid;
    int v = (gid < NN) ? deg[gid] : 0;
    sh[tid] = v;
    __syncthreads();
    for (int ofs = 1; ofs < 1024; ofs <<= 1) {
        int t = 0;
        if (tid >= ofs) t = sh[tid - ofs];
        __syncthreads();
        if (tid >= ofs) sh[tid] += t;
        __syncthreads();
    }
    part[gid] = sh[tid] - v;   // exclusive
    if (tid == 1023) bsum[blockIdx.x] = sh[1023];
}

__global__ void scan_add_kernel(const int* __restrict__ part,
                                const int* __restrict__ bsum,
                                int* __restrict__ off, int* __restrict__ cur) {
    __shared__ int sh[128];
    int tid = threadIdx.x;
    if (tid < 128) {
        int v = (tid < 98) ? bsum[tid] : 0;
        sh[tid] = v;
    }
    __syncthreads();
    if (tid < 128) {
        for (int ofs = 1; ofs < 128; ofs <<= 1) {
            int t = 0;
            if (tid >= ofs) t = sh[tid - ofs];
            __syncthreads();
            if (tid >= ofs) sh[tid] += t;
            __syncthreads();
        }
    } else {
        for (int ofs = 1; ofs < 128; ofs <<= 1) { __syncthreads(); __syncthreads(); }
    }
    __syncthreads();
    int gid = blockIdx.x * 1024 + tid;
    if (gid >= NN) return;
    int blk_excl = (blockIdx.x == 0) ? 0 : sh[blockIdx.x - 1];
    int o = part[gid] + blk_excl;
    off[gid] = o;
    cur[gid] = o;
}

__global__ void place_kernel(const int* __restrict__ src, const int* __restrict__ dst,
                             int* __restrict__ cur, int* __restrict__ edge) {
    int e = blockIdx.x * blockDim.x + threadIdx.x;
    if (e >= EE) return;
    int d = __ldg(dst + e);
    int p = atomicAdd(&cur[d], 1);
    edge[p] = __ldg(src + e);
}

// ---------------------------------------------------------------------------
// Gather: acc = (1+eps)*h[n] + sum h[src_e] over fp16 rows; fp32 accumulate;
// output plain bf16 (A-hi only). Edge loop unrolled x4 for MLP.
// ---------------------------------------------------------------------------
template <int K>
__global__ __launch_bounds__(256) void gather_kernel(
    const __half* __restrict__ hin,
    uint16_t* __restrict__ agh,
    const int* __restrict__ off, const int* __restrict__ deg,
    const int* __restrict__ edge, const float* __restrict__ eps) {
    constexpr int L = K / 8;             // lanes per node (16B each)
    const int tid = blockIdx.x * 256 + threadIdx.x;
    const int gn = tid / L;
    const int sub = tid % L;
    if (gn >= NN) return;

    float acc[8];
    const float s = 1.0f + __ldg(eps);
    {
        uint4 u = *(const uint4*)(hin + (size_t)gn * K + sub * 8);
        const __half2* hp = (const __half2*)&u;
#pragma unroll
        for (int j = 0; j < 4; j++) {
            float2 f = __half22float2(hp[j]);
            acc[j * 2 + 0] = s * f.x;
            acc[j * 2 + 1] = s * f.y;
        }
    }

    const int e0 = __ldg(off + gn);
    const int dg = __ldg(deg + gn);
    int e = 0;
    for (; e + 4 <= dg; e += 4) {
        int sn0 = __ldg(edge + e0 + e);
        int sn1 = __ldg(edge + e0 + e + 1);
        int sn2 = __ldg(edge + e0 + e + 2);
        int sn3 = __ldg(edge + e0 + e + 3);
        uint4 u0 = *(const uint4*)(hin + (size_t)sn0 * K + sub * 8);
        uint4 u1 = *(const uint4*)(hin + (size_t)sn1 * K + sub * 8);
        uint4 u2 = *(const uint4*)(hin + (size_t)sn2 * K + sub * 8);
        uint4 u3 = *(const uint4*)(hin + (size_t)sn3 * K + sub * 8);
        const __half2* p0 = (const __half2*)&u0;
        const __half2* p1 = (const __half2*)&u1;
        const __half2* p2 = (const __half2*)&u2;
        const __half2* p3 = (const __half2*)&u3;
#pragma unroll
        for (int j = 0; j < 4; j++) {
            float2 f0 = __half22float2(p0[j]);
            float2 f1 = __half22float2(p1[j]);
            float2 f2 = __half22float2(p2[j]);
            float2 f3 = __half22float2(p3[j]);
            acc[j * 2 + 0] += (f0.x + f1.x) + (f2.x + f3.x);
            acc[j * 2 + 1] += (f0.y + f1.y) + (f2.y + f3.y);
        }
    }
    for (; e < dg; e++) {
        int sn0 = __ldg(edge + e0 + e);
        uint4 ua = *(const uint4*)(hin + (size_t)sn0 * K + sub * 8);
        const __half2* pa = (const __half2*)&ua;
#pragma unroll
        for (int j = 0; j < 4; j++) {
            float2 fa = __half22float2(pa[j]);
            acc[j * 2 + 0] += fa.x;
            acc[j * 2 + 1] += fa.y;
        }
    }

    uint4 hv;
    hv.x = packbf2(acc[0], acc[1]);
    hv.y = packbf2(acc[2], acc[3]);
    hv.z = packbf2(acc[4], acc[5]);
    hv.w = packbf2(acc[6], acc[7]);
    *(uint4*)(agh + (size_t)gn * K + sub * 8) = hv;
}

// ---------------------------------------------------------------------------
// GEMM core: C[2][8][4] += A(bf16) @ (Whi + Wlo), 2-term split.
// ---------------------------------------------------------------------------
template <int KS>
__device__ __forceinline__ void do_gemm(float c[2][8][4],
                                        const uint32_t aB[2],
                                        const uint32_t bBH[4], const uint32_t bBL[4]) {
#pragma unroll
    for (int ks = 0; ks < KS; ks++) {
        const uint32_t kx = ks * 32;
        uint32_t aF[2][4];
#pragma unroll
        for (int m = 0; m < 2; m++) ldm_x4(aF[m], aB[m] ^ kx);
#pragma unroll
        for (int p = 0; p < 4; p++) {
            uint32_t bh[4], bl[4];
            ldm_x4(bh, bBH[p] ^ kx);
            ldm_x4(bl, bBL[p] ^ kx);
#pragma unroll
            for (int s = 0; s < 2; s++) {
                const int nt = 2 * p + s;
#pragma unroll
                for (int m = 0; m < 2; m++) {
                    mma_bf16(c[m][nt], aF[m], bh[s * 2], bh[s * 2 + 1]);
                    mma_bf16(c[m][nt], aF[m], bl[s * 2], bl[s * 2 + 1]);
                }
            }
        }
    }
}

// ---------------------------------------------------------------------------
// Fused GIN MLP: out = relu(A@W1+b1)@W2+b2 per 128-node tile.
// A arrives as plain bf16 from the gather. Output fp16. POOL folds h.w_out.
// ---------------------------------------------------------------------------
template <int K_IN, bool POOL>
__global__ __launch_bounds__(128) void fused_mlp_kernel(
    const uint16_t* __restrict__ Ah,
    const float* __restrict__ W1, const float* __restrict__ b1,
    const float* __restrict__ W2, const float* __restrict__ b2, int w1Rows,
    __half* __restrict__ out,
    const int* __restrict__ batch,
    const float* __restrict__ wout, float* __restrict__ outp) {
    __shared__ __align__(128) char sA[128 * 128];     // 16KB
    __shared__ __align__(128) char sW_hi[64 * 128];   // 8KB
    __shared__ __align__(128) char sW_lo[64 * 128];   // 8KB

    const int tid  = threadIdx.x;
    const int warp = tid >> 5;
    const int lane = tid & 31;
    const int qr = lane >> 2;
    const int qc = lane & 3;
    const int g  = lane >> 3;
    const int li = lane & 7;
    const int base = blockIdx.x * 128;

    const uint32_t sA_u   = smem_u32(sA);
    const uint32_t sWhi_u = smem_u32(sW_hi);
    const uint32_t sWlo_u = smem_u32(sW_lo);

    // ---- Stage A: pure 16B copies ----
    constexpr int CH = K_IN / 8;  // 16B chunks of data per row
    for (int idx = tid; idx < 128 * CH; idx += 128) {
        int row = idx / CH, cch = idx % CH;
        int gn = base + row;
        uint4 vh = make_uint4(0, 0, 0, 0);
        if (gn < NN) vh = *(const uint4*)(Ah + (size_t)gn * K_IN + cch * 8);
        *(uint4*)(sA + (rb(row) ^ (uint32_t)(cch * 16))) = vh;
    }
    // ---- Stage W1 transposed: sW[n][k] hi/lo ----
    for (int i = tid; i < 64 * 32; i += 128) {
        int n = i >> 5, c2 = i & 31;
        int k0 = c2 * 2;
        float w0  = (k0     < w1Rows) ? W1[(k0    ) * 64 + n] : 0.0f;
        float w1v = (k0 + 1 < w1Rows) ? W1[(k0 + 1) * 64 + n] : 0.0f;
        uint32_t lo, hi = packsplit(w0, w1v, lo);
        uint32_t o = rb(n) ^ (uint32_t)(k0 * 2);
        *(uint32_t*)(sW_hi + o) = hi;
        *(uint32_t*)(sW_lo + o) = lo;
    }
    __syncthreads();

    // ---- Precompute ldmatrix lane bases ----
    uint32_t aB[2];
#pragma unroll
    for (int m = 0; m < 2; m++) {
        int rowA = warp * 32 + m * 16 + li + (g & 1) * 8;
        uint32_t ka = (uint32_t)((g >> 1) * 16);
        aB[m] = sA_u + (rb(rowA) ^ ka);
    }
    uint32_t bBH[4], bBL[4];
#pragma unroll
    for (int p = 0; p < 4; p++) {
        int rowB = p * 16 + ((g >> 1) & 1) * 8 + li;
        uint32_t kb = (uint32_t)((g & 1) * 16);
        uint32_t r = rb(rowB) ^ kb;
        bBH[p] = sWhi_u + r;
        bBL[p] = sWlo_u + r;
    }

    float c[2][8][4];
#pragma unroll
    for (int m = 0; m < 2; m++)
#pragma unroll
        for (int n = 0; n < 8; n++)
#pragma unroll
            for (int j = 0; j < 4; j++) c[m][n][j] = 0.0f;

    // ---- GEMM1 ----
    do_gemm<K_IN / 16>(c, aB, bBH, bBL);

    // ---- Epilogue 1: h = relu(C+b1) -> plain bf16 into sA ----
#pragma unroll
    for (int m = 0; m < 2; m++) {
        int r0 = warp * 32 + m * 16 + qr;
        uint32_t rb0 = rb(r0), rb1 = rb(r0 + 8);
#pragma unroll
        for (int nt = 0; nt < 8; nt++) {
            uint32_t cb = (uint32_t)(nt * 16 + qc * 4);
            int col = nt * 8 + qc * 2;
            float bv0 = __ldg(b1 + col), bv1 = __ldg(b1 + col + 1);
            float v0 = fmaxf(c[m][nt][0] + bv0, 0.0f);
            float v1 = fmaxf(c[m][nt][1] + bv1, 0.0f);
            float v2 = fmaxf(c[m][nt][2] + bv0, 0.0f);
            float v3 = fmaxf(c[m][nt][3] + bv1, 0.0f);
            *(uint32_t*)(sA + (rb0 ^ cb)) = packbf2(v0, v1);
            *(uint32_t*)(sA + (rb1 ^ cb)) = packbf2(v2, v3);
        }
    }
    __syncthreads();

    // ---- Restage W2 ----
    for (int i = tid; i < 64 * 32; i += 128) {
        int n = i >> 5, c2 = i & 31;
        int k0 = c2 * 2;
        uint32_t lo, hi = packsplit(W2[k0 * 64 + n], W2[(k0 + 1) * 64 + n], lo);
        uint32_t o = rb(n) ^ (uint32_t)(k0 * 2);
        *(uint32_t*)(sW_hi + o) = hi;
        *(uint32_t*)(sW_lo + o) = lo;
    }
    __syncthreads();

#pragma unroll
    for (int m = 0; m < 2; m++)
#pragma unroll
        for (int n = 0; n < 8; n++)
#pragma unroll
            for (int j = 0; j < 4; j++) c[m][n][j] = 0.0f;

    // ---- GEMM2 ----
    do_gemm<4>(c, aB, bBH, bBL);

    // ---- Epilogue 2 ----
    if (!POOL) {
#pragma unroll
        for (int m = 0; m < 2; m++) {
            int r0 = warp * 32 + m * 16 + qr;
            int gn0 = base + r0, gn1 = gn0 + 8;
#pragma unroll
            for (int nt = 0; nt < 8; nt++) {
                int col = nt * 8 + qc * 2;
                float bv0 = __ldg(b2 + col), bv1 = __ldg(b2 + col + 1);
                if (gn0 < NN)
                    *(__half2*)(out + (size_t)gn0 * 64 + col) =
                        __floats2half2_rn(c[m][nt][0] + bv0, c[m][nt][1] + bv1);
                if (gn1 < NN)
                    *(__half2*)(out + (size_t)gn1 * 64 + col) =
                        __floats2half2_rn(c[m][nt][2] + bv0, c[m][nt][3] + bv1);
            }
        }
    } else {
#pragma unroll
        for (int m = 0; m < 2; m++) {
            int r0 = warp * 32 + m * 16 + qr;
            int gn0 = base + r0, gn1 = gn0 + 8;
            float s0 = 0.0f, s1 = 0.0f;
#pragma unroll
            for (int nt = 0; nt < 8; nt++) {
                int col = nt * 8 + qc * 2;
                float bv0 = __ldg(b2 + col), bv1 = __ldg(b2 + col + 1);
                float w0 = __ldg(wout + col), w1 = __ldg(wout + col + 1);
                s0 += (c[m][nt][0] + bv0) * w0 + (c[m][nt][1] + bv1) * w1;
                s1 += (c[m][nt][2] + bv0) * w0 + (c[m][nt][3] + bv1) * w1;
            }
            s0 += __shfl_xor_sync(0xFFFFFFFF, s0, 1);
            s0 += __shfl_xor_sync(0xFFFFFFFF, s0, 2);
            s1 += __shfl_xor_sync(0xFFFFFFFF, s1, 1);
            s1 += __shfl_xor_sync(0xFFFFFFFF, s1, 2);
            if (qc == 0) {
                if (gn0 < NN) atomicAdd(&outp[__ldg(batch + gn0)], s0);
                if (gn1 < NN) atomicAdd(&outp[__ldg(batch + gn1)], s1);
            }
        }
    }
}

// ---------------------------------------------------------------------------
extern "C" void kernel_launch(void* const* d_in, const int* in_sizes, int n_in,
                              void* d_out, int out_size) {
    const float* x     = (const float*)d_in[0];
    const int*   ei    = (const int*)d_in[1];   // [2, E]
    const int*   batch = (const int*)d_in[2];
    const float* eps0  = (const float*)d_in[3];
    const float* w1_0  = (const float*)d_in[4];
    const float* b1_0  = (const float*)d_in[5];
    const float* w2_0  = (const float*)d_in[6];
    const float* b2_0  = (const float*)d_in[7];
    const float* eps_r = (const float*)d_in[8];
    const float* w1_r  = (const float*)d_in[9];
    const float* b1_r  = (const float*)d_in[10];
    const float* w2_r  = (const float*)d_in[11];
    const float* b2_r  = (const float*)d_in[12];
    const float* w_out = (const float*)d_in[13];
    const float* b_out = (const float*)d_in[14];

    const int* src = ei;
    const int* dst = ei + EE;

    __half *xpad, *hbuf;
    uint16_t *agh;
    int *deg, *off, *cur, *edge, *part, *bsum;
    cudaGetSymbolAddress((void**)&xpad, g_xpad);
    cudaGetSymbolAddress((void**)&hbuf, g_hbuf);
    cudaGetSymbolAddress((void**)&agh,  g_aggh);
    cudaGetSymbolAddress((void**)&deg,  g_deg);
    cudaGetSymbolAddress((void**)&off,  g_off);
    cudaGetSymbolAddress((void**)&cur,  g_cur);
    cudaGetSymbolAddress((void**)&edge, g_edge);
    cudaGetSymbolAddress((void**)&part, g_part);
    cudaGetSymbolAddress((void**)&bsum, g_bsum);

    float* outp = (float*)d_out;
    const int TB = 256;
    const int mlp_grid = (NN + 127) / 128;

    // ---- CSR build (one-time) + prep: 5 launches ----
    pad_init_kernel<<<(NN * 32 + TB - 1) / TB, TB>>>(x, xpad, deg);
    count_deg_kernel<<<(EE + TB - 1) / TB, TB>>>(dst, deg, outp, b_out);
    scan_block_kernel<<<98, 1024>>>(deg, part, bsum);
    scan_add_kernel<<<98, 1024>>>(part, bsum, off, cur);
    place_kernel<<<(EE + TB - 1) / TB, TB>>>(src, dst, cur, edge);

    // ---- Layer 0 (K=32) ----
    gather_kernel<32><<<(NN * 4 + 255) / 256, 256>>>(xpad, agh, off, deg, edge, eps0);
    fused_mlp_kernel<32, false><<<mlp_grid, 128>>>(agh, w1_0, b1_0, w2_0, b2_0, 30,
                                                   hbuf, nullptr, nullptr, nullptr);
    // ---- Layers 1..2 ----
    for (int i = 0; i < 2; i++) {
        gather_kernel<64><<<(NN * 8 + 255) / 256, 256>>>(hbuf, agh, off, deg, edge, eps_r + i);
        fused_mlp_kernel<64, false><<<mlp_grid, 128>>>(agh, w1_r + i * 4096, b1_r + i * 64,
                                                       w2_r + i * 4096, b2_r + i * 64, 64,
                                                       hbuf, nullptr, nullptr, nullptr);
    }
    // ---- Layer 3 (fused pool) ----
    gather_kernel<64><<<(NN * 8 + 255) / 256, 256>>>(hbuf, agh, off, deg, edge, eps_r + 2);
    fused_mlp_kernel<64, true><<<mlp_grid, 128>>>(agh, w1_r + 8192, b1_r + 128,
                                                  w2_r + 8192, b2_r + 128, 64,
                                                  nullptr, batch, w_out, outp);
}